// round 7
// baseline (speedup 1.0000x reference)
#include <cuda_runtime.h>
#include <cuda_bf16.h>
#include <cuda_fp16.h>
#include <math.h>
#include <stdint.h>

// ---------------------------------------------------------------------------
// HybridMambaBlock: B=2, L=1024, D_MODEL=768, D=1536, N=16, K_CONV=4, R=48
// p layout per token (52272): [z:0..1536) [u:1536..3072) [dth:3072..3120)
//                             [B:3120..27696) [C:27696..52272)
// ---------------------------------------------------------------------------

#define BATCH   2
#define SEQLEN  1024
#define NROWS   (BATCH*SEQLEN)      // 2048
#define DMODEL  768
#define DINNER  1536
#define NSTATE  16
#define DTRANK  48
#define PTOT    52272
#define OFF_Z   0
#define OFF_U   1536
#define OFF_DTH 3072
#define OFF_B   3120
#define OFF_C   27696

// scratch (device-global: no allocations allowed)
__device__ float g_p[(size_t)NROWS * PTOT];          // ~428 MB
__device__ float g_dtpre[(size_t)NROWS * DINNER];
__device__ float g_dt[(size_t)NROWS * DINNER];
__device__ float g_uc[(size_t)NROWS * DINNER];
__device__ float g_y[(size_t)NROWS * DINNER];
__device__ float g_res[(size_t)NROWS * DINNER];
__device__ __half g_wh[(size_t)PTOT * DMODEL];       // 80 MB fp16 W_in
__device__ __half g_xnh[(size_t)NROWS * DMODEL];
__device__ __half g_xh[(size_t)NROWS * DMODEL];
__device__ __half g_xl[(size_t)NROWS * DMODEL];
__device__ __half g_wres[(size_t)DINNER * DMODEL];
__device__ __half g_wout[(size_t)DMODEL * DINNER];
__device__ __half g_gnh[(size_t)NROWS * DINNER];
__device__ __half g_gnl[(size_t)NROWS * DINNER];

// ---------------------------------------------------------------------------
// helpers
// ---------------------------------------------------------------------------
__device__ __forceinline__ uint32_t smem_u32(const void* p) {
    uint32_t a;
    asm("{ .reg .u64 t; cvta.to.shared.u64 t, %1; cvt.u32.u64 %0, t; }"
        : "=r"(a) : "l"(p));
    return a;
}

#define LDSM4(r0, r1, r2, r3, addr) \
    asm volatile("ldmatrix.sync.aligned.m8n8.x4.shared.b16 {%0,%1,%2,%3}, [%4];" \
        : "=r"(r0), "=r"(r1), "=r"(r2), "=r"(r3) : "r"(addr))

#define MMA16816F16(d, a, b) \
    asm volatile("mma.sync.aligned.m16n8k16.row.col.f32.f16.f16.f32 " \
        "{%0,%1,%2,%3}, {%4,%5,%6,%7}, {%8,%9}, {%0,%1,%2,%3};" \
        : "+f"((d)[0]), "+f"((d)[1]), "+f"((d)[2]), "+f"((d)[3]) \
        : "r"((a)[0]), "r"((a)[1]), "r"((a)[2]), "r"((a)[3]), \
          "r"((b)[0]), "r"((b)[1]))

#define CP_ASYNC16(dst, src, zf) \
    asm volatile("cp.async.cg.shared.global [%0], [%1], 16, %2;" \
        :: "r"(dst), "l"(src), "r"(zf))
#define CP_COMMIT()  asm volatile("cp.async.commit_group;" ::: "memory")
#define CP_WAIT1()   asm volatile("cp.async.wait_group 1;" ::: "memory")

#define ROWB    80
#define TILE_S  (128 * ROWB)         // 10240 B per 128x32 fp16 tile
#define NSTG    3

// ---------------------------------------------------------------------------
// 1-term fp16 HMMA GEMM (big projection):  C[m,n] = sum_k Ah[m,k] * Wh[n,k]
// CTA 128x128, BK=32, 3-stage cp.async, 8 warps of 32x64.
// ---------------------------------------------------------------------------
#define STAGE1_S (2 * TILE_S)        // Ah Wh

__global__ void __launch_bounds__(256, 1) gemm1(
    const __half* __restrict__ Ah, const __half* __restrict__ Wh,
    float* __restrict__ C, int N, int K, int kiter)
{
    extern __shared__ char sm[];
    uint32_t sb = smem_u32(sm);
    int tid = threadIdx.x;
    int wid = tid >> 5;
    int lane = tid & 31;
    int m0 = blockIdx.x * 128;
    int n0 = blockIdx.y * 128;
    int wm = wid >> 1;
    int wn = wid & 1;

    auto load_stage = [&](int stage, int k0) {
        uint32_t sdst = sb + stage * STAGE1_S;
        #pragma unroll
        for (int j = 0; j < 4; j++) {
            int job = tid + j * 256;     // 0..1023
            int tile = job >> 9;         // 0=Ah 1=Wh
            int rem  = job & 511;
            int r    = rem >> 2;
            int cc   = rem & 3;
            const __half* src;
            int zf = 16;
            if (tile == 0) src = Ah + (size_t)(m0 + r) * K + k0 + cc * 8;
            else {
                int n = n0 + r;
                if (n >= N) { n = N - 1; zf = 0; }
                src = Wh + (size_t)n * K + k0 + cc * 8;
            }
            uint32_t d = sdst + tile * TILE_S + r * ROWB + cc * 16;
            CP_ASYNC16(d, src, zf);
        }
        CP_COMMIT();
    };

    float c[2][8][4];
    #pragma unroll
    for (int mt = 0; mt < 2; mt++)
        #pragma unroll
        for (int nt = 0; nt < 8; nt++)
            #pragma unroll
            for (int q = 0; q < 4; q++) c[mt][nt][q] = 0.f;

    load_stage(0, 0);
    load_stage(1, 32);

    for (int it = 0; it < kiter; it++) {
        CP_WAIT1();
        __syncthreads();

        int k0n = (it + 2) * 32;
        if (k0n < K) load_stage((it + 2) % NSTG, k0n);
        else CP_COMMIT();

        uint32_t st = sb + (it % NSTG) * STAGE1_S;

        #pragma unroll
        for (int kk = 0; kk < 32; kk += 16) {
            uint32_t aH[2][4], bH[8][2];
            #pragma unroll
            for (int mt = 0; mt < 2; mt++) {
                int row = wm * 32 + mt * 16 + (lane & 15);
                int ch  = (kk >> 3) + (lane >> 4);
                uint32_t addr = st + row * ROWB + ch * 16;
                LDSM4(aH[mt][0], aH[mt][1], aH[mt][2], aH[mt][3], addr);
            }
            #pragma unroll
            for (int np = 0; np < 4; np++) {
                int nrow = wn * 64 + np * 16 + (lane & 7) + ((lane >> 4) << 3);
                int ch   = (kk >> 3) + ((lane >> 3) & 1);
                uint32_t addr = st + TILE_S + nrow * ROWB + ch * 16;
                LDSM4(bH[np * 2][0], bH[np * 2][1], bH[np * 2 + 1][0], bH[np * 2 + 1][1], addr);
            }
            #pragma unroll
            for (int mt = 0; mt < 2; mt++)
                #pragma unroll
                for (int nt = 0; nt < 8; nt++)
                    MMA16816F16(c[mt][nt], aH[mt], bH[nt]);
        }
        __syncthreads();
    }

    int g = lane >> 2, t4 = lane & 3;
    #pragma unroll
    for (int mt = 0; mt < 2; mt++) {
        int row = m0 + wm * 32 + mt * 16 + g;
        #pragma unroll
        for (int nt = 0; nt < 8; nt++) {
            int col = n0 + wn * 64 + nt * 8 + t4 * 2;
            if (col < N) {
                float2 v0 = make_float2(c[mt][nt][0], c[mt][nt][1]);
                float2 v1 = make_float2(c[mt][nt][2], c[mt][nt][3]);
                *(float2*)(C + (size_t)row * N + col) = v0;
                *(float2*)(C + (size_t)(row + 8) * N + col) = v1;
            }
        }
    }
}

// ---------------------------------------------------------------------------
// 2-term split-fp16 HMMA GEMM (res/out): C = (Ah+Al) @ Wh^T
// ---------------------------------------------------------------------------
#define STAGE2_S (3 * TILE_S)        // Ah Al Wh

__global__ void __launch_bounds__(256, 1) gemm2(
    const __half* __restrict__ Ah, const __half* __restrict__ Al,
    const __half* __restrict__ Wh, float* __restrict__ C,
    int N, int K, int kiter)
{
    extern __shared__ char sm[];
    uint32_t sb = smem_u32(sm);
    int tid = threadIdx.x;
    int wid = tid >> 5;
    int lane = tid & 31;
    int m0 = blockIdx.x * 128;
    int n0 = blockIdx.y * 128;
    int wm = wid >> 1;
    int wn = wid & 1;

    auto load_stage = [&](int stage, int k0) {
        uint32_t sdst = sb + stage * STAGE2_S;
        #pragma unroll
        for (int j = 0; j < 6; j++) {
            int job = tid + j * 256;
            int tile = job >> 9;         // 0=Ah 1=Al 2=Wh
            int rem  = job & 511;
            int r    = rem >> 2;
            int cc   = rem & 3;
            const __half* src;
            int zf = 16;
            if (tile == 0)      src = Ah + (size_t)(m0 + r) * K + k0 + cc * 8;
            else if (tile == 1) src = Al + (size_t)(m0 + r) * K + k0 + cc * 8;
            else {
                int n = n0 + r;
                if (n >= N) { n = N - 1; zf = 0; }
                src = Wh + (size_t)n * K + k0 + cc * 8;
            }
            uint32_t d = sdst + tile * TILE_S + r * ROWB + cc * 16;
            CP_ASYNC16(d, src, zf);
        }
        CP_COMMIT();
    };

    float c[2][8][4];
    #pragma unroll
    for (int mt = 0; mt < 2; mt++)
        #pragma unroll
        for (int nt = 0; nt < 8; nt++)
            #pragma unroll
            for (int q = 0; q < 4; q++) c[mt][nt][q] = 0.f;

    load_stage(0, 0);
    load_stage(1, 32);

    for (int it = 0; it < kiter; it++) {
        CP_WAIT1();
        __syncthreads();

        int k0n = (it + 2) * 32;
        if (k0n < K) load_stage((it + 2) % NSTG, k0n);
        else CP_COMMIT();

        uint32_t st = sb + (it % NSTG) * STAGE2_S;

        #pragma unroll
        for (int kk = 0; kk < 32; kk += 16) {
            uint32_t aH[2][4], aL[2][4], bH[8][2];
            #pragma unroll
            for (int mt = 0; mt < 2; mt++) {
                int row = wm * 32 + mt * 16 + (lane & 15);
                int ch  = (kk >> 3) + (lane >> 4);
                uint32_t addr = st + row * ROWB + ch * 16;
                LDSM4(aH[mt][0], aH[mt][1], aH[mt][2], aH[mt][3], addr);
                LDSM4(aL[mt][0], aL[mt][1], aL[mt][2], aL[mt][3], addr + TILE_S);
            }
            #pragma unroll
            for (int np = 0; np < 4; np++) {
                int nrow = wn * 64 + np * 16 + (lane & 7) + ((lane >> 4) << 3);
                int ch   = (kk >> 3) + ((lane >> 3) & 1);
                uint32_t addr = st + 2 * TILE_S + nrow * ROWB + ch * 16;
                LDSM4(bH[np * 2][0], bH[np * 2][1], bH[np * 2 + 1][0], bH[np * 2 + 1][1], addr);
            }
            #pragma unroll
            for (int mt = 0; mt < 2; mt++)
                #pragma unroll
                for (int nt = 0; nt < 8; nt++) {
                    MMA16816F16(c[mt][nt], aH[mt], bH[nt]);
                    MMA16816F16(c[mt][nt], aL[mt], bH[nt]);
                }
        }
        __syncthreads();
    }

    int g = lane >> 2, t4 = lane & 3;
    #pragma unroll
    for (int mt = 0; mt < 2; mt++) {
        int row = m0 + wm * 32 + mt * 16 + g;
        #pragma unroll
        for (int nt = 0; nt < 8; nt++) {
            int col = n0 + wn * 64 + nt * 8 + t4 * 2;
            if (col < N) {
                float2 v0 = make_float2(c[mt][nt][0], c[mt][nt][1]);
                float2 v1 = make_float2(c[mt][nt][2], c[mt][nt][3]);
                *(float2*)(C + (size_t)row * N + col) = v0;
                *(float2*)(C + (size_t)(row + 8) * N + col) = v1;
            }
        }
    }
}

// ---------------------------------------------------------------------------
// fp32 -> fp16 (hi only)
// ---------------------------------------------------------------------------
__global__ void __launch_bounds__(256) convert_h(
    const float* __restrict__ W, __half* __restrict__ Wh)
{
    size_t i4 = (size_t)blockIdx.x * 256 + threadIdx.x;
    float4 v = ((const float4*)W)[i4];
    __half2* o = (__half2*)Wh;
    o[i4 * 2 + 0] = __floats2half2_rn(v.x, v.y);
    o[i4 * 2 + 1] = __floats2half2_rn(v.z, v.w);
}

// ---------------------------------------------------------------------------
// fp32 -> (hi, lo) fp16 split
// ---------------------------------------------------------------------------
__global__ void __launch_bounds__(256) convert_split(
    const float* __restrict__ X, __half* __restrict__ Xh, __half* __restrict__ Xl)
{
    size_t i4 = (size_t)blockIdx.x * 256 + threadIdx.x;
    float4 v = ((const float4*)X)[i4];
    __half h0 = __float2half_rn(v.x), h1 = __float2half_rn(v.y);
    __half h2 = __float2half_rn(v.z), h3 = __float2half_rn(v.w);
    __half2* oh = (__half2*)Xh;
    __half2* ol = (__half2*)Xl;
    oh[i4 * 2 + 0] = __halves2half2(h0, h1);
    oh[i4 * 2 + 1] = __halves2half2(h2, h3);
    ol[i4 * 2 + 0] = __floats2half2_rn(v.x - __half2float(h0), v.y - __half2float(h1));
    ol[i4 * 2 + 1] = __floats2half2_rn(v.z - __half2float(h2), v.w - __half2float(h3));
}

// ---------------------------------------------------------------------------
// block reduction helper (256 threads)
// ---------------------------------------------------------------------------
__device__ __forceinline__ float block_reduce_sum256(float v, float* sh) {
    int lane = threadIdx.x & 31;
    int w    = threadIdx.x >> 5;
    #pragma unroll
    for (int o = 16; o > 0; o >>= 1) v += __shfl_xor_sync(0xffffffffu, v, o);
    if (lane == 0) sh[w] = v;
    __syncthreads();
    if (w == 0) {
        v = (lane < 8) ? sh[lane] : 0.0f;
        #pragma unroll
        for (int o = 4; o > 0; o >>= 1) v += __shfl_xor_sync(0xffffffffu, v, o);
        if (lane == 0) sh[0] = v;
    }
    __syncthreads();
    return sh[0];
}

// ---------------------------------------------------------------------------
// LayerNorm: one block per row of 768; outputs fp16 xn
// ---------------------------------------------------------------------------
__global__ void __launch_bounds__(256) ln_kernel(
    const float* __restrict__ x, const float* __restrict__ w,
    const float* __restrict__ b, __half* __restrict__ oh)
{
    __shared__ float sh[32];
    int r = blockIdx.x;
    const float* xr = x + (size_t)r * DMODEL;
    float s = 0.f, ss = 0.f;
    float v[3];
    #pragma unroll
    for (int i = 0; i < 3; i++) {
        v[i] = xr[threadIdx.x + i * 256];
        s  += v[i];
        ss += v[i] * v[i];
    }
    s  = block_reduce_sum256(s, sh);
    __syncthreads();
    ss = block_reduce_sum256(ss, sh);
    float mu  = s * (1.0f / DMODEL);
    float var = ss * (1.0f / DMODEL) - mu * mu;
    float inv = rsqrtf(var + 1e-5f);
    #pragma unroll
    for (int i = 0; i < 3; i++) {
        int c = threadIdx.x + i * 256;
        float val = (v[i] - mu) * inv * w[c] + b[c];
        oh[(size_t)r * DMODEL + c] = __float2half_rn(val);
    }
}

// ---------------------------------------------------------------------------
// SIMT fp32 GEMM (dt projection only, K=48): C[m,n] = sum_k A[m,k]*B[n,k]
// ---------------------------------------------------------------------------
#define GBM 128
#define GBN 128
#define GBK 16
__global__ void __launch_bounds__(256) gemm_nt(
    const float* __restrict__ A, const float* __restrict__ B,
    float* __restrict__ C, int M, int N, int K, int lda, int ldb, int ldc)
{
    __shared__ float As[GBK][GBM + 4];
    __shared__ float Bs[GBK][GBN + 4];

    int tid = threadIdx.x;
    int tx = tid & 15;
    int ty = tid >> 4;
    int m0 = blockIdx.y * GBM;
    int n0 = blockIdx.x * GBN;
    int lrow = tid >> 2;
    int lc4  = tid & 3;

    float acc[8][8];
    #pragma unroll
    for (int i = 0; i < 8; i++)
        #pragma unroll
        for (int j = 0; j < 8; j++) acc[i][j] = 0.f;

    for (int k0 = 0; k0 < K; k0 += GBK) {
        #pragma unroll
        for (int i = 0; i < 2; i++) {
            int row = lrow + i * 64;
            float4 v = *(const float4*)(A + (size_t)(m0 + row) * lda + k0 + lc4 * 4);
            As[lc4 * 4 + 0][row] = v.x;
            As[lc4 * 4 + 1][row] = v.y;
            As[lc4 * 4 + 2][row] = v.z;
            As[lc4 * 4 + 3][row] = v.w;
        }
        #pragma unroll
        for (int i = 0; i < 2; i++) {
            int row = lrow + i * 64;
            int n = n0 + row;
            float4 v = make_float4(0.f, 0.f, 0.f, 0.f);
            if (n < N)
                v = *(const float4*)(B + (size_t)n * ldb + k0 + lc4 * 4);
            Bs[lc4 * 4 + 0][row] = v.x;
            Bs[lc4 * 4 + 1][row] = v.y;
            Bs[lc4 * 4 + 2][row] = v.z;
            Bs[lc4 * 4 + 3][row] = v.w;
        }
        __syncthreads();
        #pragma unroll
        for (int kk = 0; kk < GBK; kk++) {
            float a[8], b[8];
            #pragma unroll
            for (int i = 0; i < 8; i++) a[i] = As[kk][ty * 8 + i];
            #pragma unroll
            for (int j = 0; j < 8; j++) b[j] = Bs[kk][tx * 8 + j];
            #pragma unroll
            for (int i = 0; i < 8; i++)
                #pragma unroll
                for (int j = 0; j < 8; j++)
                    acc[i][j] = fmaf(a[i], b[j], acc[i][j]);
        }
        __syncthreads();
    }

    #pragma unroll
    for (int i = 0; i < 8; i++) {
        int m = m0 + ty * 8 + i;
        float* cp = C + (size_t)m * ldc + n0 + tx * 8;
        float4 v0 = make_float4(acc[i][0], acc[i][1], acc[i][2], acc[i][3]);
        float4 v1 = make_float4(acc[i][4], acc[i][5], acc[i][6], acc[i][7]);
        *(float4*)(cp + 0) = v0;
        *(float4*)(cp + 4) = v1;
    }
}

// ---------------------------------------------------------------------------
// Depthwise causal conv (K=4) + dt = clip(softplus(dtpre + dt_bias))
// ---------------------------------------------------------------------------
__global__ void __launch_bounds__(256) convdt_kernel(
    const float* __restrict__ conv_w, const float* __restrict__ conv_b,
    const float* __restrict__ dt_bias,
    const float* __restrict__ p, const float* __restrict__ dtpre,
    float* __restrict__ uc, float* __restrict__ dt)
{
    int idx = blockIdx.x * 256 + threadIdx.x;
    int d = idx % DINNER;
    int r = idx / DINNER;
    int l = r & (SEQLEN - 1);

    const float* pu = p + (size_t)r * PTOT + OFF_U + d;
    float acc = conv_b[d];
    #pragma unroll
    for (int k = 0; k < 4; k++) {
        int lp = l - 3 + k;
        if (lp >= 0)
            acc = fmaf(pu[(ptrdiff_t)(k - 3) * PTOT], conv_w[d * 4 + k], acc);
    }
    uc[idx] = acc;

    float xv = dtpre[idx] + dt_bias[d];
    float sp = fmaxf(xv, 0.f) + log1pf(expf(-fabsf(xv)));
    dt[idx] = fminf(fmaxf(sp, 1e-4f), 1.0f);
}

// ---------------------------------------------------------------------------
// SSM scan: 16 threads per (b,d). unroll 4 -> 16 independent LDGs in flight
// ---------------------------------------------------------------------------
__global__ void __launch_bounds__(256) scan_kernel(
    const float* __restrict__ p, const float* __restrict__ dt,
    const float* __restrict__ uc, const float* __restrict__ A_log,
    const float* __restrict__ Dskip, float* __restrict__ y)
{
    int tid = threadIdx.x;
    int n = tid & 15;
    int g = tid >> 4;
    int d = blockIdx.x * 16 + g;
    int b = blockIdx.y;

    float Ad  = -expf(A_log[d * NSTATE + n]);
    float dsk = Dskip[d];
    float h = 0.f;

    const float* pB  = p  + (size_t)(b * SEQLEN) * PTOT + OFF_B + d * NSTATE + n;
    const float* pC  = pB + (OFF_C - OFF_B);
    const float* pdt = dt + (size_t)(b * SEQLEN) * DINNER + d;
    const float* puc = uc + (size_t)(b * SEQLEN) * DINNER + d;
    float*       py  = y  + (size_t)(b * SEQLEN) * DINNER + d;

    for (int t0 = 0; t0 < SEQLEN; t0 += 4) {
        // batch all loads for 4 timesteps (16 independent LDGs)
        float dtv[4], ucv[4], Bv[4], Cv[4];
        #pragma unroll
        for (int u = 0; u < 4; u++) {
            dtv[u] = __ldg(pdt + (size_t)u * DINNER);
            ucv[u] = __ldg(puc + (size_t)u * DINNER);
            Bv[u]  = __ldg(pB  + (size_t)u * PTOT);
            Cv[u]  = __ldg(pC  + (size_t)u * PTOT);
        }
        #pragma unroll
        for (int u = 0; u < 4; u++) {
            float dA = expf(dtv[u] * Ad);
            h = fmaf(dA, h, dtv[u] * ucv[u] * Bv[u]);
            float part = Cv[u] * h;
            part += __shfl_xor_sync(0xffffffffu, part, 8, 16);
            part += __shfl_xor_sync(0xffffffffu, part, 4, 16);
            part += __shfl_xor_sync(0xffffffffu, part, 2, 16);
            part += __shfl_xor_sync(0xffffffffu, part, 1, 16);
            if (n == 0) py[(size_t)u * DINNER] = fmaf(dsk, ucv[u], part);
        }
        pB += 4 * PTOT; pC += 4 * PTOT;
        pdt += 4 * DINNER; puc += 4 * DINNER; py += 4 * DINNER;
    }
}

// ---------------------------------------------------------------------------
// gate: g = y*silu(z); gn = g * rsqrt(mean(g^2)+1e-6) * norm_w + res
// outputs split-fp16 for the output projection
// ---------------------------------------------------------------------------
__global__ void __launch_bounds__(256) gate_kernel(
    const float* __restrict__ p, const float* __restrict__ y,
    const float* __restrict__ res, const float* __restrict__ norm_w,
    __half* __restrict__ gnh, __half* __restrict__ gnl)
{
    __shared__ float sh[32];
    int r = blockIdx.x;
    const float* zrow = p + (size_t)r * PTOT + OFF_Z;
    const float* yrow = y + (size_t)r * DINNER;
    float gv[6];
    float ss = 0.f;
    #pragma unroll
    for (int i = 0; i < 6; i++) {
        int c = threadIdx.x + i * 256;
        float z = zrow[c];
        float sil = z / (1.f + expf(-z));
        float gg = yrow[c] * sil;
        gv[i] = gg;
        ss += gg * gg;
    }
    ss = block_reduce_sum256(ss, sh);
    float s = rsqrtf(ss * (1.0f / DINNER) + 1e-6f);
    #pragma unroll
    for (int i = 0; i < 6; i++) {
        int c = threadIdx.x + i * 256;
        float val = gv[i] * s * norm_w[c] + res[(size_t)r * DINNER + c];
        __half h = __float2half_rn(val);
        gnh[(size_t)r * DINNER + c] = h;
        gnl[(size_t)r * DINNER + c] = __float2half_rn(val - __half2float(h));
    }
}

// ---------------------------------------------------------------------------
// host
// ---------------------------------------------------------------------------
extern "C" void kernel_launch(void* const* d_in, const int* in_sizes, int n_in,
                              void* d_out, int out_size)
{
    const float* x       = (const float*)d_in[0];
    const float* ln_w    = (const float*)d_in[1];
    const float* ln_b    = (const float*)d_in[2];
    const float* W_in    = (const float*)d_in[3];
    const float* W_dt    = (const float*)d_in[4];
    const float* conv_w  = (const float*)d_in[5];
    const float* conv_b  = (const float*)d_in[6];
    const float* A_log   = (const float*)d_in[7];
    const float* Dskip   = (const float*)d_in[8];
    const float* dt_bias = (const float*)d_in[9];
    const float* norm_w  = (const float*)d_in[10];
    const float* W_res   = (const float*)d_in[11];
    const float* W_out   = (const float*)d_in[12];
    float* out = (float*)d_out;

    float *p, *dtpre, *dt, *uc, *y, *res;
    __half *wh, *xnh, *xh, *xl, *wres, *wout, *gnh, *gnl;
    cudaGetSymbolAddress((void**)&p,     g_p);
    cudaGetSymbolAddress((void**)&dtpre, g_dtpre);
    cudaGetSymbolAddress((void**)&dt,    g_dt);
    cudaGetSymbolAddress((void**)&uc,    g_uc);
    cudaGetSymbolAddress((void**)&y,     g_y);
    cudaGetSymbolAddress((void**)&res,   g_res);
    cudaGetSymbolAddress((void**)&wh,    g_wh);
    cudaGetSymbolAddress((void**)&xnh,   g_xnh);
    cudaGetSymbolAddress((void**)&xh,    g_xh);
    cudaGetSymbolAddress((void**)&xl,    g_xl);
    cudaGetSymbolAddress((void**)&wres,  g_wres);
    cudaGetSymbolAddress((void**)&wout,  g_wout);
    cudaGetSymbolAddress((void**)&gnh,   g_gnh);
    cudaGetSymbolAddress((void**)&gnl,   g_gnl);

    static bool attr_set = false;
    if (!attr_set) {
        cudaFuncSetAttribute(gemm1, cudaFuncAttributeMaxDynamicSharedMemorySize,
                             NSTG * STAGE1_S);
        cudaFuncSetAttribute(gemm2, cudaFuncAttributeMaxDynamicSharedMemorySize,
                             NSTG * STAGE2_S);
        attr_set = true;
    }

    // Launch order arranged so gemm1 is the 4th launch (ncu profiles launch #4).
    // 1. W_in convert
    convert_h<<<(size_t)PTOT * DMODEL / 4 / 256, 256>>>(W_in, wh);
    // 2. LayerNorm (outputs fp16 xn)
    ln_kernel<<<NROWS, 256>>>(x, ln_w, ln_b, xnh);
    // 3. W_res convert
    convert_h<<<(size_t)DINNER * DMODEL / 4 / 256, 256>>>(W_res, wres);
    // 4. big input projection (1-term fp16): p = xn @ W_in^T  [2048, 52272]
    gemm1<<<dim3(NROWS / 128, (PTOT + 127) / 128), 256, NSTG * STAGE1_S>>>(
        xnh, wh, p, PTOT, DMODEL, DMODEL / 32);
    // 5-6. remaining converts
    convert_h<<<(size_t)DMODEL * DINNER / 4 / 256, 256>>>(W_out, wout);
    convert_split<<<(size_t)NROWS * DMODEL / 4 / 256, 256>>>(x, xh, xl);
    // 7. dt pre-projection
    gemm_nt<<<dim3(DINNER / GBN, NROWS / GBM), 256>>>(
        p + OFF_DTH, W_dt, dtpre, NROWS, DINNER, DTRANK, PTOT, DTRANK, DINNER);
    // 8. conv + softplus(dt)
    convdt_kernel<<<(NROWS * DINNER) / 256, 256>>>(
        conv_w, conv_b, dt_bias, p, dtpre, uc, dt);
    // 9. sequential SSM scan
    scan_kernel<<<dim3(DINNER / 16, BATCH), 256>>>(p, dt, uc, A_log, Dskip, y);
    // 10. residual projection (2-term)
    gemm2<<<dim3(NROWS / 128, DINNER / 128), 256, NSTG * STAGE2_S>>>(
        xh, xl, wres, res, DINNER, DMODEL, DMODEL / 32);
    // 11. gate + RMSNorm + residual
    gate_kernel<<<NROWS, 256>>>(p, y, res, norm_w, gnh, gnl);
    // 12. output projection (2-term)
    gemm2<<<dim3(NROWS / 128, DMODEL / 128), 256, NSTG * STAGE2_S>>>(
        gnh, gnl, wout, out, DMODEL, DINNER, DINNER / 32);
}

// round 8
// speedup vs baseline: 1.1903x; 1.1903x over previous
#include <cuda_runtime.h>
#include <cuda_bf16.h>
#include <cuda_fp16.h>
#include <math.h>
#include <stdint.h>

// ---------------------------------------------------------------------------
// HybridMambaBlock: B=2, L=1024, D_MODEL=768, D=1536, N=16, K_CONV=4, R=48
// p layout per token (52272): [z:0..1536) [u:1536..3072) [dth:3072..3120)
//                             [B:3120..27696) [C:27696..52272)
// ---------------------------------------------------------------------------

#define BATCH   2
#define SEQLEN  1024
#define NROWS   (BATCH*SEQLEN)      // 2048
#define DMODEL  768
#define DINNER  1536
#define NSTATE  16
#define DTRANK  48
#define PTOT    52272
#define OFF_Z   0
#define OFF_U   1536
#define OFF_DTH 3072
#define OFF_B   3120
#define OFF_C   27696

// scratch (device-global: no allocations allowed)
__device__ float g_p[(size_t)NROWS * PTOT];          // ~428 MB
__device__ float g_dtpre[(size_t)NROWS * DINNER];
__device__ float g_dt[(size_t)NROWS * DINNER];
__device__ float g_uc[(size_t)NROWS * DINNER];
__device__ float g_y[(size_t)NROWS * DINNER];
__device__ float g_res[(size_t)NROWS * DINNER];
__device__ __half g_wh[(size_t)PTOT * DMODEL];       // 80 MB fp16 W_in
__device__ __half g_xnh[(size_t)NROWS * DMODEL];
__device__ __half g_xh[(size_t)NROWS * DMODEL];
__device__ __half g_xl[(size_t)NROWS * DMODEL];
__device__ __half g_wres[(size_t)DINNER * DMODEL];
__device__ __half g_wout[(size_t)DMODEL * DINNER];
__device__ __half g_gnh[(size_t)NROWS * DINNER];
__device__ __half g_gnl[(size_t)NROWS * DINNER];

// ---------------------------------------------------------------------------
// helpers
// ---------------------------------------------------------------------------
__device__ __forceinline__ uint32_t smem_u32(const void* p) {
    uint32_t a;
    asm("{ .reg .u64 t; cvta.to.shared.u64 t, %1; cvt.u32.u64 %0, t; }"
        : "=r"(a) : "l"(p));
    return a;
}

#define LDSM4(r0, r1, r2, r3, addr) \
    asm volatile("ldmatrix.sync.aligned.m8n8.x4.shared.b16 {%0,%1,%2,%3}, [%4];" \
        : "=r"(r0), "=r"(r1), "=r"(r2), "=r"(r3) : "r"(addr))

#define MMA16816F16(d, a, b) \
    asm volatile("mma.sync.aligned.m16n8k16.row.col.f32.f16.f16.f32 " \
        "{%0,%1,%2,%3}, {%4,%5,%6,%7}, {%8,%9}, {%0,%1,%2,%3};" \
        : "+f"((d)[0]), "+f"((d)[1]), "+f"((d)[2]), "+f"((d)[3]) \
        : "r"((a)[0]), "r"((a)[1]), "r"((a)[2]), "r"((a)[3]), \
          "r"((b)[0]), "r"((b)[1]))

#define CP_ASYNC16(dst, src, zf) \
    asm volatile("cp.async.cg.shared.global [%0], [%1], 16, %2;" \
        :: "r"(dst), "l"(src), "r"(zf))
#define CP_COMMIT()  asm volatile("cp.async.commit_group;" ::: "memory")
#define CP_WAIT1()   asm volatile("cp.async.wait_group 1;" ::: "memory")

#define ROWB    80
#define TILE_S  (128 * ROWB)         // 10240 B per 128x32 fp16 tile
#define NSTG    3

// ---------------------------------------------------------------------------
// 1-term fp16 HMMA GEMM (big projection):  C[m,n] = sum_k Ah[m,k] * Wh[n,k]
// CTA 128x128, BK=32, 3-stage cp.async, 8 warps of 32x64.
// 2 CTAs/SM (60KB smem each, <=128 regs) -> 4 warps/SMSP to hide LDSM latency.
// ---------------------------------------------------------------------------
#define STAGE1_S (2 * TILE_S)        // Ah Wh

__global__ void __launch_bounds__(256, 2) gemm1(
    const __half* __restrict__ Ah, const __half* __restrict__ Wh,
    float* __restrict__ C, int N, int K, int kiter)
{
    extern __shared__ char sm[];
    uint32_t sb = smem_u32(sm);
    int tid = threadIdx.x;
    int wid = tid >> 5;
    int lane = tid & 31;
    int m0 = blockIdx.x * 128;
    int n0 = blockIdx.y * 128;
    int wm = wid >> 1;
    int wn = wid & 1;

    auto load_stage = [&](int stage, int k0) {
        uint32_t sdst = sb + stage * STAGE1_S;
        #pragma unroll
        for (int j = 0; j < 4; j++) {
            int job = tid + j * 256;     // 0..1023
            int tile = job >> 9;         // 0=Ah 1=Wh
            int rem  = job & 511;
            int r    = rem >> 2;
            int cc   = rem & 3;
            const __half* src;
            int zf = 16;
            if (tile == 0) src = Ah + (size_t)(m0 + r) * K + k0 + cc * 8;
            else {
                int n = n0 + r;
                if (n >= N) { n = N - 1; zf = 0; }
                src = Wh + (size_t)n * K + k0 + cc * 8;
            }
            uint32_t d = sdst + tile * TILE_S + r * ROWB + cc * 16;
            CP_ASYNC16(d, src, zf);
        }
        CP_COMMIT();
    };

    float c[2][8][4];
    #pragma unroll
    for (int mt = 0; mt < 2; mt++)
        #pragma unroll
        for (int nt = 0; nt < 8; nt++)
            #pragma unroll
            for (int q = 0; q < 4; q++) c[mt][nt][q] = 0.f;

    load_stage(0, 0);
    load_stage(1, 32);

    for (int it = 0; it < kiter; it++) {
        CP_WAIT1();
        __syncthreads();

        int k0n = (it + 2) * 32;
        if (k0n < K) load_stage((it + 2) % NSTG, k0n);
        else CP_COMMIT();

        uint32_t st = sb + (it % NSTG) * STAGE1_S;

        #pragma unroll
        for (int kk = 0; kk < 32; kk += 16) {
            uint32_t aH[2][4], bH[8][2];
            #pragma unroll
            for (int mt = 0; mt < 2; mt++) {
                int row = wm * 32 + mt * 16 + (lane & 15);
                int ch  = (kk >> 3) + (lane >> 4);
                uint32_t addr = st + row * ROWB + ch * 16;
                LDSM4(aH[mt][0], aH[mt][1], aH[mt][2], aH[mt][3], addr);
            }
            #pragma unroll
            for (int np = 0; np < 4; np++) {
                int nrow = wn * 64 + np * 16 + (lane & 7) + ((lane >> 4) << 3);
                int ch   = (kk >> 3) + ((lane >> 3) & 1);
                uint32_t addr = st + TILE_S + nrow * ROWB + ch * 16;
                LDSM4(bH[np * 2][0], bH[np * 2][1], bH[np * 2 + 1][0], bH[np * 2 + 1][1], addr);
            }
            #pragma unroll
            for (int mt = 0; mt < 2; mt++)
                #pragma unroll
                for (int nt = 0; nt < 8; nt++)
                    MMA16816F16(c[mt][nt], aH[mt], bH[nt]);
        }
        __syncthreads();
    }

    int g = lane >> 2, t4 = lane & 3;
    #pragma unroll
    for (int mt = 0; mt < 2; mt++) {
        int row = m0 + wm * 32 + mt * 16 + g;
        #pragma unroll
        for (int nt = 0; nt < 8; nt++) {
            int col = n0 + wn * 64 + nt * 8 + t4 * 2;
            if (col < N) {
                float2 v0 = make_float2(c[mt][nt][0], c[mt][nt][1]);
                float2 v1 = make_float2(c[mt][nt][2], c[mt][nt][3]);
                *(float2*)(C + (size_t)row * N + col) = v0;
                *(float2*)(C + (size_t)(row + 8) * N + col) = v1;
            }
        }
    }
}

// ---------------------------------------------------------------------------
// 2-term split-fp16 HMMA GEMM (res/out): C = (Ah+Al) @ Wh^T
// ---------------------------------------------------------------------------
#define STAGE2_S (3 * TILE_S)        // Ah Al Wh

__global__ void __launch_bounds__(256, 1) gemm2(
    const __half* __restrict__ Ah, const __half* __restrict__ Al,
    const __half* __restrict__ Wh, float* __restrict__ C,
    int N, int K, int kiter)
{
    extern __shared__ char sm[];
    uint32_t sb = smem_u32(sm);
    int tid = threadIdx.x;
    int wid = tid >> 5;
    int lane = tid & 31;
    int m0 = blockIdx.x * 128;
    int n0 = blockIdx.y * 128;
    int wm = wid >> 1;
    int wn = wid & 1;

    auto load_stage = [&](int stage, int k0) {
        uint32_t sdst = sb + stage * STAGE2_S;
        #pragma unroll
        for (int j = 0; j < 6; j++) {
            int job = tid + j * 256;
            int tile = job >> 9;         // 0=Ah 1=Al 2=Wh
            int rem  = job & 511;
            int r    = rem >> 2;
            int cc   = rem & 3;
            const __half* src;
            int zf = 16;
            if (tile == 0)      src = Ah + (size_t)(m0 + r) * K + k0 + cc * 8;
            else if (tile == 1) src = Al + (size_t)(m0 + r) * K + k0 + cc * 8;
            else {
                int n = n0 + r;
                if (n >= N) { n = N - 1; zf = 0; }
                src = Wh + (size_t)n * K + k0 + cc * 8;
            }
            uint32_t d = sdst + tile * TILE_S + r * ROWB + cc * 16;
            CP_ASYNC16(d, src, zf);
        }
        CP_COMMIT();
    };

    float c[2][8][4];
    #pragma unroll
    for (int mt = 0; mt < 2; mt++)
        #pragma unroll
        for (int nt = 0; nt < 8; nt++)
            #pragma unroll
            for (int q = 0; q < 4; q++) c[mt][nt][q] = 0.f;

    load_stage(0, 0);
    load_stage(1, 32);

    for (int it = 0; it < kiter; it++) {
        CP_WAIT1();
        __syncthreads();

        int k0n = (it + 2) * 32;
        if (k0n < K) load_stage((it + 2) % NSTG, k0n);
        else CP_COMMIT();

        uint32_t st = sb + (it % NSTG) * STAGE2_S;

        #pragma unroll
        for (int kk = 0; kk < 32; kk += 16) {
            uint32_t aH[2][4], aL[2][4], bH[8][2];
            #pragma unroll
            for (int mt = 0; mt < 2; mt++) {
                int row = wm * 32 + mt * 16 + (lane & 15);
                int ch  = (kk >> 3) + (lane >> 4);
                uint32_t addr = st + row * ROWB + ch * 16;
                LDSM4(aH[mt][0], aH[mt][1], aH[mt][2], aH[mt][3], addr);
                LDSM4(aL[mt][0], aL[mt][1], aL[mt][2], aL[mt][3], addr + TILE_S);
            }
            #pragma unroll
            for (int np = 0; np < 4; np++) {
                int nrow = wn * 64 + np * 16 + (lane & 7) + ((lane >> 4) << 3);
                int ch   = (kk >> 3) + ((lane >> 3) & 1);
                uint32_t addr = st + 2 * TILE_S + nrow * ROWB + ch * 16;
                LDSM4(bH[np * 2][0], bH[np * 2][1], bH[np * 2 + 1][0], bH[np * 2 + 1][1], addr);
            }
            #pragma unroll
            for (int mt = 0; mt < 2; mt++)
                #pragma unroll
                for (int nt = 0; nt < 8; nt++) {
                    MMA16816F16(c[mt][nt], aH[mt], bH[nt]);
                    MMA16816F16(c[mt][nt], aL[mt], bH[nt]);
                }
        }
        __syncthreads();
    }

    int g = lane >> 2, t4 = lane & 3;
    #pragma unroll
    for (int mt = 0; mt < 2; mt++) {
        int row = m0 + wm * 32 + mt * 16 + g;
        #pragma unroll
        for (int nt = 0; nt < 8; nt++) {
            int col = n0 + wn * 64 + nt * 8 + t4 * 2;
            if (col < N) {
                float2 v0 = make_float2(c[mt][nt][0], c[mt][nt][1]);
                float2 v1 = make_float2(c[mt][nt][2], c[mt][nt][3]);
                *(float2*)(C + (size_t)row * N + col) = v0;
                *(float2*)(C + (size_t)(row + 8) * N + col) = v1;
            }
        }
    }
}

// ---------------------------------------------------------------------------
// fp32 -> fp16 (hi only)
// ---------------------------------------------------------------------------
__global__ void __launch_bounds__(256) convert_h(
    const float* __restrict__ W, __half* __restrict__ Wh)
{
    size_t i4 = (size_t)blockIdx.x * 256 + threadIdx.x;
    float4 v = ((const float4*)W)[i4];
    __half2* o = (__half2*)Wh;
    o[i4 * 2 + 0] = __floats2half2_rn(v.x, v.y);
    o[i4 * 2 + 1] = __floats2half2_rn(v.z, v.w);
}

// ---------------------------------------------------------------------------
// fp32 -> (hi, lo) fp16 split
// ---------------------------------------------------------------------------
__global__ void __launch_bounds__(256) convert_split(
    const float* __restrict__ X, __half* __restrict__ Xh, __half* __restrict__ Xl)
{
    size_t i4 = (size_t)blockIdx.x * 256 + threadIdx.x;
    float4 v = ((const float4*)X)[i4];
    __half h0 = __float2half_rn(v.x), h1 = __float2half_rn(v.y);
    __half h2 = __float2half_rn(v.z), h3 = __float2half_rn(v.w);
    __half2* oh = (__half2*)Xh;
    __half2* ol = (__half2*)Xl;
    oh[i4 * 2 + 0] = __halves2half2(h0, h1);
    oh[i4 * 2 + 1] = __halves2half2(h2, h3);
    ol[i4 * 2 + 0] = __floats2half2_rn(v.x - __half2float(h0), v.y - __half2float(h1));
    ol[i4 * 2 + 1] = __floats2half2_rn(v.z - __half2float(h2), v.w - __half2float(h3));
}

// ---------------------------------------------------------------------------
// block reduction helper (256 threads)
// ---------------------------------------------------------------------------
__device__ __forceinline__ float block_reduce_sum256(float v, float* sh) {
    int lane = threadIdx.x & 31;
    int w    = threadIdx.x >> 5;
    #pragma unroll
    for (int o = 16; o > 0; o >>= 1) v += __shfl_xor_sync(0xffffffffu, v, o);
    if (lane == 0) sh[w] = v;
    __syncthreads();
    if (w == 0) {
        v = (lane < 8) ? sh[lane] : 0.0f;
        #pragma unroll
        for (int o = 4; o > 0; o >>= 1) v += __shfl_xor_sync(0xffffffffu, v, o);
        if (lane == 0) sh[0] = v;
    }
    __syncthreads();
    return sh[0];
}

// ---------------------------------------------------------------------------
// LayerNorm: one block per row of 768; outputs fp16 xn
// ---------------------------------------------------------------------------
__global__ void __launch_bounds__(256) ln_kernel(
    const float* __restrict__ x, const float* __restrict__ w,
    const float* __restrict__ b, __half* __restrict__ oh)
{
    __shared__ float sh[32];
    int r = blockIdx.x;
    const float* xr = x + (size_t)r * DMODEL;
    float s = 0.f, ss = 0.f;
    float v[3];
    #pragma unroll
    for (int i = 0; i < 3; i++) {
        v[i] = xr[threadIdx.x + i * 256];
        s  += v[i];
        ss += v[i] * v[i];
    }
    s  = block_reduce_sum256(s, sh);
    __syncthreads();
    ss = block_reduce_sum256(ss, sh);
    float mu  = s * (1.0f / DMODEL);
    float var = ss * (1.0f / DMODEL) - mu * mu;
    float inv = rsqrtf(var + 1e-5f);
    #pragma unroll
    for (int i = 0; i < 3; i++) {
        int c = threadIdx.x + i * 256;
        float val = (v[i] - mu) * inv * w[c] + b[c];
        oh[(size_t)r * DMODEL + c] = __float2half_rn(val);
    }
}

// ---------------------------------------------------------------------------
// SIMT fp32 GEMM (dt projection only, K=48): C[m,n] = sum_k A[m,k]*B[n,k]
// ---------------------------------------------------------------------------
#define GBM 128
#define GBN 128
#define GBK 16
__global__ void __launch_bounds__(256) gemm_nt(
    const float* __restrict__ A, const float* __restrict__ B,
    float* __restrict__ C, int M, int N, int K, int lda, int ldb, int ldc)
{
    __shared__ float As[GBK][GBM + 4];
    __shared__ float Bs[GBK][GBN + 4];

    int tid = threadIdx.x;
    int tx = tid & 15;
    int ty = tid >> 4;
    int m0 = blockIdx.y * GBM;
    int n0 = blockIdx.x * GBN;
    int lrow = tid >> 2;
    int lc4  = tid & 3;

    float acc[8][8];
    #pragma unroll
    for (int i = 0; i < 8; i++)
        #pragma unroll
        for (int j = 0; j < 8; j++) acc[i][j] = 0.f;

    for (int k0 = 0; k0 < K; k0 += GBK) {
        #pragma unroll
        for (int i = 0; i < 2; i++) {
            int row = lrow + i * 64;
            float4 v = *(const float4*)(A + (size_t)(m0 + row) * lda + k0 + lc4 * 4);
            As[lc4 * 4 + 0][row] = v.x;
            As[lc4 * 4 + 1][row] = v.y;
            As[lc4 * 4 + 2][row] = v.z;
            As[lc4 * 4 + 3][row] = v.w;
        }
        #pragma unroll
        for (int i = 0; i < 2; i++) {
            int row = lrow + i * 64;
            int n = n0 + row;
            float4 v = make_float4(0.f, 0.f, 0.f, 0.f);
            if (n < N)
                v = *(const float4*)(B + (size_t)n * ldb + k0 + lc4 * 4);
            Bs[lc4 * 4 + 0][row] = v.x;
            Bs[lc4 * 4 + 1][row] = v.y;
            Bs[lc4 * 4 + 2][row] = v.z;
            Bs[lc4 * 4 + 3][row] = v.w;
        }
        __syncthreads();
        #pragma unroll
        for (int kk = 0; kk < GBK; kk++) {
            float a[8], b[8];
            #pragma unroll
            for (int i = 0; i < 8; i++) a[i] = As[kk][ty * 8 + i];
            #pragma unroll
            for (int j = 0; j < 8; j++) b[j] = Bs[kk][tx * 8 + j];
            #pragma unroll
            for (int i = 0; i < 8; i++)
                #pragma unroll
                for (int j = 0; j < 8; j++)
                    acc[i][j] = fmaf(a[i], b[j], acc[i][j]);
        }
        __syncthreads();
    }

    #pragma unroll
    for (int i = 0; i < 8; i++) {
        int m = m0 + ty * 8 + i;
        float* cp = C + (size_t)m * ldc + n0 + tx * 8;
        float4 v0 = make_float4(acc[i][0], acc[i][1], acc[i][2], acc[i][3]);
        float4 v1 = make_float4(acc[i][4], acc[i][5], acc[i][6], acc[i][7]);
        *(float4*)(cp + 0) = v0;
        *(float4*)(cp + 4) = v1;
    }
}

// ---------------------------------------------------------------------------
// Depthwise causal conv (K=4) + dt = clip(softplus(dtpre + dt_bias))
// ---------------------------------------------------------------------------
__global__ void __launch_bounds__(256) convdt_kernel(
    const float* __restrict__ conv_w, const float* __restrict__ conv_b,
    const float* __restrict__ dt_bias,
    const float* __restrict__ p, const float* __restrict__ dtpre,
    float* __restrict__ uc, float* __restrict__ dt)
{
    int idx = blockIdx.x * 256 + threadIdx.x;
    int d = idx % DINNER;
    int r = idx / DINNER;
    int l = r & (SEQLEN - 1);

    const float* pu = p + (size_t)r * PTOT + OFF_U + d;
    float acc = conv_b[d];
    #pragma unroll
    for (int k = 0; k < 4; k++) {
        int lp = l - 3 + k;
        if (lp >= 0)
            acc = fmaf(pu[(ptrdiff_t)(k - 3) * PTOT], conv_w[d * 4 + k], acc);
    }
    uc[idx] = acc;

    float xv = dtpre[idx] + dt_bias[d];
    float sp = fmaxf(xv, 0.f) + log1pf(expf(-fabsf(xv)));
    dt[idx] = fminf(fmaxf(sp, 1e-4f), 1.0f);
}

// ---------------------------------------------------------------------------
// SSM scan: 16 threads per (b,d). unroll 4 -> 16 independent LDGs in flight
// ---------------------------------------------------------------------------
__global__ void __launch_bounds__(256) scan_kernel(
    const float* __restrict__ p, const float* __restrict__ dt,
    const float* __restrict__ uc, const float* __restrict__ A_log,
    const float* __restrict__ Dskip, float* __restrict__ y)
{
    int tid = threadIdx.x;
    int n = tid & 15;
    int g = tid >> 4;
    int d = blockIdx.x * 16 + g;
    int b = blockIdx.y;

    float Ad  = -expf(A_log[d * NSTATE + n]);
    float dsk = Dskip[d];
    float h = 0.f;

    const float* pB  = p  + (size_t)(b * SEQLEN) * PTOT + OFF_B + d * NSTATE + n;
    const float* pC  = pB + (OFF_C - OFF_B);
    const float* pdt = dt + (size_t)(b * SEQLEN) * DINNER + d;
    const float* puc = uc + (size_t)(b * SEQLEN) * DINNER + d;
    float*       py  = y  + (size_t)(b * SEQLEN) * DINNER + d;

    for (int t0 = 0; t0 < SEQLEN; t0 += 4) {
        float dtv[4], ucv[4], Bv[4], Cv[4];
        #pragma unroll
        for (int u = 0; u < 4; u++) {
            dtv[u] = __ldg(pdt + (size_t)u * DINNER);
            ucv[u] = __ldg(puc + (size_t)u * DINNER);
            Bv[u]  = __ldg(pB  + (size_t)u * PTOT);
            Cv[u]  = __ldg(pC  + (size_t)u * PTOT);
        }
        #pragma unroll
        for (int u = 0; u < 4; u++) {
            float dA = expf(dtv[u] * Ad);
            h = fmaf(dA, h, dtv[u] * ucv[u] * Bv[u]);
            float part = Cv[u] * h;
            part += __shfl_xor_sync(0xffffffffu, part, 8, 16);
            part += __shfl_xor_sync(0xffffffffu, part, 4, 16);
            part += __shfl_xor_sync(0xffffffffu, part, 2, 16);
            part += __shfl_xor_sync(0xffffffffu, part, 1, 16);
            if (n == 0) py[(size_t)u * DINNER] = fmaf(dsk, ucv[u], part);
        }
        pB += 4 * PTOT; pC += 4 * PTOT;
        pdt += 4 * DINNER; puc += 4 * DINNER; py += 4 * DINNER;
    }
}

// ---------------------------------------------------------------------------
// gate: g = y*silu(z); gn = g * rsqrt(mean(g^2)+1e-6) * norm_w + res
// outputs split-fp16 for the output projection
// ---------------------------------------------------------------------------
__global__ void __launch_bounds__(256) gate_kernel(
    const float* __restrict__ p, const float* __restrict__ y,
    const float* __restrict__ res, const float* __restrict__ norm_w,
    __half* __restrict__ gnh, __half* __restrict__ gnl)
{
    __shared__ float sh[32];
    int r = blockIdx.x;
    const float* zrow = p + (size_t)r * PTOT + OFF_Z;
    const float* yrow = y + (size_t)r * DINNER;
    float gv[6];
    float ss = 0.f;
    #pragma unroll
    for (int i = 0; i < 6; i++) {
        int c = threadIdx.x + i * 256;
        float z = zrow[c];
        float sil = z / (1.f + expf(-z));
        float gg = yrow[c] * sil;
        gv[i] = gg;
        ss += gg * gg;
    }
    ss = block_reduce_sum256(ss, sh);
    float s = rsqrtf(ss * (1.0f / DINNER) + 1e-6f);
    #pragma unroll
    for (int i = 0; i < 6; i++) {
        int c = threadIdx.x + i * 256;
        float val = gv[i] * s * norm_w[c] + res[(size_t)r * DINNER + c];
        __half h = __float2half_rn(val);
        gnh[(size_t)r * DINNER + c] = h;
        gnl[(size_t)r * DINNER + c] = __float2half_rn(val - __half2float(h));
    }
}

// ---------------------------------------------------------------------------
// host
// ---------------------------------------------------------------------------
extern "C" void kernel_launch(void* const* d_in, const int* in_sizes, int n_in,
                              void* d_out, int out_size)
{
    const float* x       = (const float*)d_in[0];
    const float* ln_w    = (const float*)d_in[1];
    const float* ln_b    = (const float*)d_in[2];
    const float* W_in    = (const float*)d_in[3];
    const float* W_dt    = (const float*)d_in[4];
    const float* conv_w  = (const float*)d_in[5];
    const float* conv_b  = (const float*)d_in[6];
    const float* A_log   = (const float*)d_in[7];
    const float* Dskip   = (const float*)d_in[8];
    const float* dt_bias = (const float*)d_in[9];
    const float* norm_w  = (const float*)d_in[10];
    const float* W_res   = (const float*)d_in[11];
    const float* W_out   = (const float*)d_in[12];
    float* out = (float*)d_out;

    float *p, *dtpre, *dt, *uc, *y, *res;
    __half *wh, *xnh, *xh, *xl, *wres, *wout, *gnh, *gnl;
    cudaGetSymbolAddress((void**)&p,     g_p);
    cudaGetSymbolAddress((void**)&dtpre, g_dtpre);
    cudaGetSymbolAddress((void**)&dt,    g_dt);
    cudaGetSymbolAddress((void**)&uc,    g_uc);
    cudaGetSymbolAddress((void**)&y,     g_y);
    cudaGetSymbolAddress((void**)&res,   g_res);
    cudaGetSymbolAddress((void**)&wh,    g_wh);
    cudaGetSymbolAddress((void**)&xnh,   g_xnh);
    cudaGetSymbolAddress((void**)&xh,    g_xh);
    cudaGetSymbolAddress((void**)&xl,    g_xl);
    cudaGetSymbolAddress((void**)&wres,  g_wres);
    cudaGetSymbolAddress((void**)&wout,  g_wout);
    cudaGetSymbolAddress((void**)&gnh,   g_gnh);
    cudaGetSymbolAddress((void**)&gnl,   g_gnl);

    static bool attr_set = false;
    if (!attr_set) {
        cudaFuncSetAttribute(gemm1, cudaFuncAttributeMaxDynamicSharedMemorySize,
                             NSTG * STAGE1_S);
        cudaFuncSetAttribute(gemm2, cudaFuncAttributeMaxDynamicSharedMemorySize,
                             NSTG * STAGE2_S);
        attr_set = true;
    }

    // Launch order arranged so gemm1 is the 4th launch (ncu profiles launch #4).
    // 1. W_in convert
    convert_h<<<(size_t)PTOT * DMODEL / 4 / 256, 256>>>(W_in, wh);
    // 2. LayerNorm (outputs fp16 xn)
    ln_kernel<<<NROWS, 256>>>(x, ln_w, ln_b, xnh);
    // 3. W_res convert
    convert_h<<<(size_t)DINNER * DMODEL / 4 / 256, 256>>>(W_res, wres);
    // 4. big input projection (1-term fp16): p = xn @ W_in^T  [2048, 52272]
    gemm1<<<dim3(NROWS / 128, (PTOT + 127) / 128), 256, NSTG * STAGE1_S>>>(
        xnh, wh, p, PTOT, DMODEL, DMODEL / 32);
    // 5-6. remaining converts
    convert_h<<<(size_t)DMODEL * DINNER / 4 / 256, 256>>>(W_out, wout);
    convert_split<<<(size_t)NROWS * DMODEL / 4 / 256, 256>>>(x, xh, xl);
    // 7. dt pre-projection
    gemm_nt<<<dim3(DINNER / GBN, NROWS / GBM), 256>>>(
        p + OFF_DTH, W_dt, dtpre, NROWS, DINNER, DTRANK, PTOT, DTRANK, DINNER);
    // 8. conv + softplus(dt)
    convdt_kernel<<<(NROWS * DINNER) / 256, 256>>>(
        conv_w, conv_b, dt_bias, p, dtpre, uc, dt);
    // 9. sequential SSM scan
    scan_kernel<<<dim3(DINNER / 16, BATCH), 256>>>(p, dt, uc, A_log, Dskip, y);
    // 10. residual projection (2-term)
    gemm2<<<dim3(NROWS / 128, DINNER / 128), 256, NSTG * STAGE2_S>>>(
        xh, xl, wres, res, DINNER, DMODEL, DMODEL / 32);
    // 11. gate + RMSNorm + residual
    gate_kernel<<<NROWS, 256>>>(p, y, res, norm_w, gnh, gnl);
    // 12. output projection (2-term)
    gemm2<<<dim3(NROWS / 128, DMODEL / 128), 256, NSTG * STAGE2_S>>>(
        gnh, gnl, wout, out, DMODEL, DINNER, DINNER / 32);
}

// round 11
// speedup vs baseline: 1.6533x; 1.3890x over previous
#include <cuda_runtime.h>
#include <cuda_bf16.h>
#include <cuda_fp16.h>
#include <math.h>
#include <stdint.h>

// ---------------------------------------------------------------------------
// HybridMambaBlock: B=2, L=1024, D_MODEL=768, D=1536, N=16, K_CONV=4, R=48
// p layout per token (52272): [z:0..1536) [u:1536..3072) [dth:3072..3120)
//                             [B:3120..27696) [C:27696..52272)
// ---------------------------------------------------------------------------

#define BATCH   2
#define SEQLEN  1024
#define NROWS   (BATCH*SEQLEN)      // 2048
#define DMODEL  768
#define DINNER  1536
#define NSTATE  16
#define DTRANK  48
#define PTOT    52272
#define OFF_Z   0
#define OFF_U   1536
#define OFF_DTH 3072
#define OFF_B   3120
#define OFF_C   27696

// scratch (device-global: no allocations allowed)
__device__ float g_p[(size_t)NROWS * PTOT];          // ~428 MB
__device__ float g_dtpre[(size_t)NROWS * DINNER];
__device__ float g_dt[(size_t)NROWS * DINNER];
__device__ float g_uc[(size_t)NROWS * DINNER];
__device__ float g_y[(size_t)NROWS * DINNER];
__device__ float g_res[(size_t)NROWS * DINNER];
__device__ __half g_wh[(size_t)PTOT * DMODEL];       // 80 MB fp16 W_in
__device__ __half g_xnh[(size_t)NROWS * DMODEL];
__device__ __half g_xh[(size_t)NROWS * DMODEL];
__device__ __half g_xl[(size_t)NROWS * DMODEL];
__device__ __half g_wres[(size_t)DINNER * DMODEL];
__device__ __half g_wout[(size_t)DMODEL * DINNER];
__device__ __half g_gnh[(size_t)NROWS * DINNER];
__device__ __half g_gnl[(size_t)NROWS * DINNER];

// ---------------------------------------------------------------------------
// helpers
// ---------------------------------------------------------------------------
__device__ __forceinline__ uint32_t smem_u32(const void* p) {
    uint32_t a;
    asm("{ .reg .u64 t; cvta.to.shared.u64 t, %1; cvt.u32.u64 %0, t; }"
        : "=r"(a) : "l"(p));
    return a;
}

#define LDSM4(r0, r1, r2, r3, addr) \
    asm volatile("ldmatrix.sync.aligned.m8n8.x4.shared.b16 {%0,%1,%2,%3}, [%4];" \
        : "=r"(r0), "=r"(r1), "=r"(r2), "=r"(r3) : "r"(addr))

#define MMA16816F16(d, a, b) \
    asm volatile("mma.sync.aligned.m16n8k16.row.col.f32.f16.f16.f32 " \
        "{%0,%1,%2,%3}, {%4,%5,%6,%7}, {%8,%9}, {%0,%1,%2,%3};" \
        : "+f"((d)[0]), "+f"((d)[1]), "+f"((d)[2]), "+f"((d)[3]) \
        : "r"((a)[0]), "r"((a)[1]), "r"((a)[2]), "r"((a)[3]), \
          "r"((b)[0]), "r"((b)[1]))

#define CP_ASYNC16(dst, src, zf) \
    asm volatile("cp.async.cg.shared.global [%0], [%1], 16, %2;" \
        :: "r"(dst), "l"(src), "r"(zf))
#define CP_COMMIT()  asm volatile("cp.async.commit_group;" ::: "memory")
#define CP_WAIT1()   asm volatile("cp.async.wait_group 1;" ::: "memory")

#define ROWB    80
#define TILE_S  (128 * ROWB)         // 10240 B per 128x32 fp16 tile
#define NSTG    3

// ---------------------------------------------------------------------------
// 1-term fp16 HMMA GEMM (big projection):  C[m,n] = sum_k Ah[m,k] * Wh[n,k]
// CTA 128x128, BK=32, 3-stage cp.async, 8 warps of 32x64, 2 CTAs/SM.
// At the mma.sync issue floor (~520us) — do not touch.
// ---------------------------------------------------------------------------
#define STAGE1_S (2 * TILE_S)        // Ah Wh

__global__ void __launch_bounds__(256, 2) gemm1(
    const __half* __restrict__ Ah, const __half* __restrict__ Wh,
    float* __restrict__ C, int N, int K, int kiter)
{
    extern __shared__ char sm[];
    uint32_t sb = smem_u32(sm);
    int tid = threadIdx.x;
    int wid = tid >> 5;
    int lane = tid & 31;
    int m0 = blockIdx.x * 128;
    int n0 = blockIdx.y * 128;
    int wm = wid >> 1;
    int wn = wid & 1;

    auto load_stage = [&](int stage, int k0) {
        uint32_t sdst = sb + stage * STAGE1_S;
        #pragma unroll
        for (int j = 0; j < 4; j++) {
            int job = tid + j * 256;     // 0..1023
            int tile = job >> 9;         // 0=Ah 1=Wh
            int rem  = job & 511;
            int r    = rem >> 2;
            int cc   = rem & 3;
            const __half* src;
            int zf = 16;
            if (tile == 0) src = Ah + (size_t)(m0 + r) * K + k0 + cc * 8;
            else {
                int n = n0 + r;
                if (n >= N) { n = N - 1; zf = 0; }
                src = Wh + (size_t)n * K + k0 + cc * 8;
            }
            uint32_t d = sdst + tile * TILE_S + r * ROWB + cc * 16;
            CP_ASYNC16(d, src, zf);
        }
        CP_COMMIT();
    };

    float c[2][8][4];
    #pragma unroll
    for (int mt = 0; mt < 2; mt++)
        #pragma unroll
        for (int nt = 0; nt < 8; nt++)
            #pragma unroll
            for (int q = 0; q < 4; q++) c[mt][nt][q] = 0.f;

    load_stage(0, 0);
    load_stage(1, 32);

    for (int it = 0; it < kiter; it++) {
        CP_WAIT1();
        __syncthreads();

        int k0n = (it + 2) * 32;
        if (k0n < K) load_stage((it + 2) % NSTG, k0n);
        else CP_COMMIT();

        uint32_t st = sb + (it % NSTG) * STAGE1_S;

        #pragma unroll
        for (int kk = 0; kk < 32; kk += 16) {
            uint32_t aH[2][4], bH[8][2];
            #pragma unroll
            for (int mt = 0; mt < 2; mt++) {
                int row = wm * 32 + mt * 16 + (lane & 15);
                int ch  = (kk >> 3) + (lane >> 4);
                uint32_t addr = st + row * ROWB + ch * 16;
                LDSM4(aH[mt][0], aH[mt][1], aH[mt][2], aH[mt][3], addr);
            }
            #pragma unroll
            for (int np = 0; np < 4; np++) {
                int nrow = wn * 64 + np * 16 + (lane & 7) + ((lane >> 4) << 3);
                int ch   = (kk >> 3) + ((lane >> 3) & 1);
                uint32_t addr = st + TILE_S + nrow * ROWB + ch * 16;
                LDSM4(bH[np * 2][0], bH[np * 2][1], bH[np * 2 + 1][0], bH[np * 2 + 1][1], addr);
            }
            #pragma unroll
            for (int mt = 0; mt < 2; mt++)
                #pragma unroll
                for (int nt = 0; nt < 8; nt++)
                    MMA16816F16(c[mt][nt], aH[mt], bH[nt]);
        }
        __syncthreads();
    }

    int g = lane >> 2, t4 = lane & 3;
    #pragma unroll
    for (int mt = 0; mt < 2; mt++) {
        int row = m0 + wm * 32 + mt * 16 + g;
        #pragma unroll
        for (int nt = 0; nt < 8; nt++) {
            int col = n0 + wn * 64 + nt * 8 + t4 * 2;
            if (col < N) {
                float2 v0 = make_float2(c[mt][nt][0], c[mt][nt][1]);
                float2 v1 = make_float2(c[mt][nt][2], c[mt][nt][3]);
                *(float2*)(C + (size_t)row * N + col) = v0;
                *(float2*)(C + (size_t)(row + 8) * N + col) = v1;
            }
        }
    }
}

// ---------------------------------------------------------------------------
// 2-term split-fp16 HMMA GEMM (res/out): C = (Ah+Al) @ Wh^T
// ---------------------------------------------------------------------------
#define STAGE2_S (3 * TILE_S)        // Ah Al Wh

__global__ void __launch_bounds__(256, 1) gemm2(
    const __half* __restrict__ Ah, const __half* __restrict__ Al,
    const __half* __restrict__ Wh, float* __restrict__ C,
    int N, int K, int kiter)
{
    extern __shared__ char sm[];
    uint32_t sb = smem_u32(sm);
    int tid = threadIdx.x;
    int wid = tid >> 5;
    int lane = tid & 31;
    int m0 = blockIdx.x * 128;
    int n0 = blockIdx.y * 128;
    int wm = wid >> 1;
    int wn = wid & 1;

    auto load_stage = [&](int stage, int k0) {
        uint32_t sdst = sb + stage * STAGE2_S;
        #pragma unroll
        for (int j = 0; j < 6; j++) {
            int job = tid + j * 256;
            int tile = job >> 9;         // 0=Ah 1=Al 2=Wh
            int rem  = job & 511;
            int r    = rem >> 2;
            int cc   = rem & 3;
            const __half* src;
            int zf = 16;
            if (tile == 0)      src = Ah + (size_t)(m0 + r) * K + k0 + cc * 8;
            else if (tile == 1) src = Al + (size_t)(m0 + r) * K + k0 + cc * 8;
            else {
                int n = n0 + r;
                if (n >= N) { n = N - 1; zf = 0; }
                src = Wh + (size_t)n * K + k0 + cc * 8;
            }
            uint32_t d = sdst + tile * TILE_S + r * ROWB + cc * 16;
            CP_ASYNC16(d, src, zf);
        }
        CP_COMMIT();
    };

    float c[2][8][4];
    #pragma unroll
    for (int mt = 0; mt < 2; mt++)
        #pragma unroll
        for (int nt = 0; nt < 8; nt++)
            #pragma unroll
            for (int q = 0; q < 4; q++) c[mt][nt][q] = 0.f;

    load_stage(0, 0);
    load_stage(1, 32);

    for (int it = 0; it < kiter; it++) {
        CP_WAIT1();
        __syncthreads();

        int k0n = (it + 2) * 32;
        if (k0n < K) load_stage((it + 2) % NSTG, k0n);
        else CP_COMMIT();

        uint32_t st = sb + (it % NSTG) * STAGE2_S;

        #pragma unroll
        for (int kk = 0; kk < 32; kk += 16) {
            uint32_t aH[2][4], aL[2][4], bH[8][2];
            #pragma unroll
            for (int mt = 0; mt < 2; mt++) {
                int row = wm * 32 + mt * 16 + (lane & 15);
                int ch  = (kk >> 3) + (lane >> 4);
                uint32_t addr = st + row * ROWB + ch * 16;
                LDSM4(aH[mt][0], aH[mt][1], aH[mt][2], aH[mt][3], addr);
                LDSM4(aL[mt][0], aL[mt][1], aL[mt][2], aL[mt][3], addr + TILE_S);
            }
            #pragma unroll
            for (int np = 0; np < 4; np++) {
                int nrow = wn * 64 + np * 16 + (lane & 7) + ((lane >> 4) << 3);
                int ch   = (kk >> 3) + ((lane >> 3) & 1);
                uint32_t addr = st + 2 * TILE_S + nrow * ROWB + ch * 16;
                LDSM4(bH[np * 2][0], bH[np * 2][1], bH[np * 2 + 1][0], bH[np * 2 + 1][1], addr);
            }
            #pragma unroll
            for (int mt = 0; mt < 2; mt++)
                #pragma unroll
                for (int nt = 0; nt < 8; nt++) {
                    MMA16816F16(c[mt][nt], aH[mt], bH[nt]);
                    MMA16816F16(c[mt][nt], aL[mt], bH[nt]);
                }
        }
        __syncthreads();
    }

    int g = lane >> 2, t4 = lane & 3;
    #pragma unroll
    for (int mt = 0; mt < 2; mt++) {
        int row = m0 + wm * 32 + mt * 16 + g;
        #pragma unroll
        for (int nt = 0; nt < 8; nt++) {
            int col = n0 + wn * 64 + nt * 8 + t4 * 2;
            if (col < N) {
                float2 v0 = make_float2(c[mt][nt][0], c[mt][nt][1]);
                float2 v1 = make_float2(c[mt][nt][2], c[mt][nt][3]);
                *(float2*)(C + (size_t)row * N + col) = v0;
                *(float2*)(C + (size_t)(row + 8) * N + col) = v1;
            }
        }
    }
}

// ---------------------------------------------------------------------------
// fp32 -> fp16 (hi only): 8 floats per thread, single 16B store
// ---------------------------------------------------------------------------
__global__ void __launch_bounds__(256) convert_h(
    const float* __restrict__ W, __half* __restrict__ Wh)
{
    size_t i8 = (size_t)blockIdx.x * 256 + threadIdx.x;  // 8-float chunk idx
    const float4* W4 = (const float4*)W;
    float4 a = W4[i8 * 2 + 0];
    float4 b = W4[i8 * 2 + 1];
    __half2 h[4];
    h[0] = __floats2half2_rn(a.x, a.y);
    h[1] = __floats2half2_rn(a.z, a.w);
    h[2] = __floats2half2_rn(b.x, b.y);
    h[3] = __floats2half2_rn(b.z, b.w);
    ((uint4*)Wh)[i8] = *(uint4*)h;
}

// ---------------------------------------------------------------------------
// fp32 -> (hi, lo) fp16 split
// ---------------------------------------------------------------------------
__global__ void __launch_bounds__(256) convert_split(
    const float* __restrict__ X, __half* __restrict__ Xh, __half* __restrict__ Xl)
{
    size_t i4 = (size_t)blockIdx.x * 256 + threadIdx.x;
    float4 v = ((const float4*)X)[i4];
    __half h0 = __float2half_rn(v.x), h1 = __float2half_rn(v.y);
    __half h2 = __float2half_rn(v.z), h3 = __float2half_rn(v.w);
    __half2* oh = (__half2*)Xh;
    __half2* ol = (__half2*)Xl;
    oh[i4 * 2 + 0] = __halves2half2(h0, h1);
    oh[i4 * 2 + 1] = __halves2half2(h2, h3);
    ol[i4 * 2 + 0] = __floats2half2_rn(v.x - __half2float(h0), v.y - __half2float(h1));
    ol[i4 * 2 + 1] = __floats2half2_rn(v.z - __half2float(h2), v.w - __half2float(h3));
}

// ---------------------------------------------------------------------------
// block reduction helper (256 threads)
// ---------------------------------------------------------------------------
__device__ __forceinline__ float block_reduce_sum256(float v, float* sh) {
    int lane = threadIdx.x & 31;
    int w    = threadIdx.x >> 5;
    #pragma unroll
    for (int o = 16; o > 0; o >>= 1) v += __shfl_xor_sync(0xffffffffu, v, o);
    if (lane == 0) sh[w] = v;
    __syncthreads();
    if (w == 0) {
        v = (lane < 8) ? sh[lane] : 0.0f;
        #pragma unroll
        for (int o = 4; o > 0; o >>= 1) v += __shfl_xor_sync(0xffffffffu, v, o);
        if (lane == 0) sh[0] = v;
    }
    __syncthreads();
    return sh[0];
}

// ---------------------------------------------------------------------------
// LayerNorm: one block per row of 768; outputs fp16 xn
// ---------------------------------------------------------------------------
__global__ void __launch_bounds__(256) ln_kernel(
    const float* __restrict__ x, const float* __restrict__ w,
    const float* __restrict__ b, __half* __restrict__ oh)
{
    __shared__ float sh[32];
    int r = blockIdx.x;
    const float* xr = x + (size_t)r * DMODEL;
    float s = 0.f, ss = 0.f;
    float v[3];
    #pragma unroll
    for (int i = 0; i < 3; i++) {
        v[i] = xr[threadIdx.x + i * 256];
        s  += v[i];
        ss += v[i] * v[i];
    }
    s  = block_reduce_sum256(s, sh);
    __syncthreads();
    ss = block_reduce_sum256(ss, sh);
    float mu  = s * (1.0f / DMODEL);
    float var = ss * (1.0f / DMODEL) - mu * mu;
    float inv = rsqrtf(var + 1e-5f);
    #pragma unroll
    for (int i = 0; i < 3; i++) {
        int c = threadIdx.x + i * 256;
        float val = (v[i] - mu) * inv * w[c] + b[c];
        oh[(size_t)r * DMODEL + c] = __float2half_rn(val);
    }
}

// ---------------------------------------------------------------------------
// SIMT fp32 GEMM (dt projection only, K=48): C[m,n] = sum_k A[m,k]*B[n,k]
// ---------------------------------------------------------------------------
#define GBM 128
#define GBN 128
#define GBK 16
__global__ void __launch_bounds__(256) gemm_nt(
    const float* __restrict__ A, const float* __restrict__ B,
    float* __restrict__ C, int M, int N, int K, int lda, int ldb, int ldc)
{
    __shared__ float As[GBK][GBM + 4];
    __shared__ float Bs[GBK][GBN + 4];

    int tid = threadIdx.x;
    int tx = tid & 15;
    int ty = tid >> 4;
    int m0 = blockIdx.y * GBM;
    int n0 = blockIdx.x * GBN;
    int lrow = tid >> 2;
    int lc4  = tid & 3;

    float acc[8][8];
    #pragma unroll
    for (int i = 0; i < 8; i++)
        #pragma unroll
        for (int j = 0; j < 8; j++) acc[i][j] = 0.f;

    for (int k0 = 0; k0 < K; k0 += GBK) {
        #pragma unroll
        for (int i = 0; i < 2; i++) {
            int row = lrow + i * 64;
            float4 v = *(const float4*)(A + (size_t)(m0 + row) * lda + k0 + lc4 * 4);
            As[lc4 * 4 + 0][row] = v.x;
            As[lc4 * 4 + 1][row] = v.y;
            As[lc4 * 4 + 2][row] = v.z;
            As[lc4 * 4 + 3][row] = v.w;
        }
        #pragma unroll
        for (int i = 0; i < 2; i++) {
            int row = lrow + i * 64;
            int n = n0 + row;
            float4 v = make_float4(0.f, 0.f, 0.f, 0.f);
            if (n < N)
                v = *(const float4*)(B + (size_t)n * ldb + k0 + lc4 * 4);
            Bs[lc4 * 4 + 0][row] = v.x;
            Bs[lc4 * 4 + 1][row] = v.y;
            Bs[lc4 * 4 + 2][row] = v.z;
            Bs[lc4 * 4 + 3][row] = v.w;
        }
        __syncthreads();
        #pragma unroll
        for (int kk = 0; kk < GBK; kk++) {
            float a[8], b[8];
            #pragma unroll
            for (int i = 0; i < 8; i++) a[i] = As[kk][ty * 8 + i];
            #pragma unroll
            for (int j = 0; j < 8; j++) b[j] = Bs[kk][tx * 8 + j];
            #pragma unroll
            for (int i = 0; i < 8; i++)
                #pragma unroll
                for (int j = 0; j < 8; j++)
                    acc[i][j] = fmaf(a[i], b[j], acc[i][j]);
        }
        __syncthreads();
    }

    #pragma unroll
    for (int i = 0; i < 8; i++) {
        int m = m0 + ty * 8 + i;
        float* cp = C + (size_t)m * ldc + n0 + tx * 8;
        float4 v0 = make_float4(acc[i][0], acc[i][1], acc[i][2], acc[i][3]);
        float4 v1 = make_float4(acc[i][4], acc[i][5], acc[i][6], acc[i][7]);
        *(float4*)(cp + 0) = v0;
        *(float4*)(cp + 4) = v1;
    }
}

// ---------------------------------------------------------------------------
// Depthwise causal conv (K=4) + dt = clip(softplus(dtpre + dt_bias))
// ---------------------------------------------------------------------------
__global__ void __launch_bounds__(256) convdt_kernel(
    const float* __restrict__ conv_w, const float* __restrict__ conv_b,
    const float* __restrict__ dt_bias,
    const float* __restrict__ p, const float* __restrict__ dtpre,
    float* __restrict__ uc, float* __restrict__ dt)
{
    int idx = blockIdx.x * 256 + threadIdx.x;
    int d = idx % DINNER;
    int r = idx / DINNER;
    int l = r & (SEQLEN - 1);

    const float* pu = p + (size_t)r * PTOT + OFF_U + d;
    float acc = conv_b[d];
    #pragma unroll
    for (int k = 0; k < 4; k++) {
        int lp = l - 3 + k;
        if (lp >= 0)
            acc = fmaf(pu[(ptrdiff_t)(k - 3) * PTOT], conv_w[d * 4 + k], acc);
    }
    uc[idx] = acc;

    float xv = dtpre[idx] + dt_bias[d];
    float sp = fmaxf(xv, 0.f) + log1pf(expf(-fabsf(xv)));
    dt[idx] = fminf(fmaxf(sp, 1e-4f), 1.0f);
}

// ---------------------------------------------------------------------------
// SSM scan v2: 16 threads per (b,d), 128-thread blocks (8 groups), grid 384.
// Double-buffered software pipeline: prefetch next 8 timesteps into a second
// register buffer while computing the current 8 -> DRAM latency overlapped.
// ---------------------------------------------------------------------------
__global__ void __launch_bounds__(128) scan_kernel(
    const float* __restrict__ p, const float* __restrict__ dt,
    const float* __restrict__ uc, const float* __restrict__ A_log,
    const float* __restrict__ Dskip, float* __restrict__ y)
{
    int tid = threadIdx.x;
    int n = tid & 15;
    int g = tid >> 4;                   // 0..7
    int d = blockIdx.x * 8 + g;
    int b = blockIdx.y;

    float Ad  = -expf(A_log[d * NSTATE + n]);
    float dsk = Dskip[d];
    float h = 0.f;

    const float* pB  = p  + (size_t)(b * SEQLEN) * PTOT + OFF_B + d * NSTATE + n;
    const float* pC  = pB + (OFF_C - OFF_B);
    const float* pdt = dt + (size_t)(b * SEQLEN) * DINNER + d;
    const float* puc = uc + (size_t)(b * SEQLEN) * DINNER + d;
    float*       py  = y  + (size_t)(b * SEQLEN) * DINNER + d;

    float dtA[8], ucA[8], BvA[8], CvA[8];
    float dtB[8], ucB[8], BvB[8], CvB[8];

    // prime buffer A with t = 0..7
    #pragma unroll
    for (int u = 0; u < 8; u++) {
        dtA[u] = __ldg(pdt + (size_t)u * DINNER);
        ucA[u] = __ldg(puc + (size_t)u * DINNER);
        BvA[u] = __ldg(pB  + (size_t)u * PTOT);
        CvA[u] = __ldg(pC  + (size_t)u * PTOT);
    }

    for (int t0 = 0; t0 < SEQLEN; t0 += 16) {
        // prefetch B: t0+8 .. t0+15 (always in range, t0 <= 1008)
        #pragma unroll
        for (int u = 0; u < 8; u++) {
            dtB[u] = __ldg(pdt + (size_t)(u + 8) * DINNER);
            ucB[u] = __ldg(puc + (size_t)(u + 8) * DINNER);
            BvB[u] = __ldg(pB  + (size_t)(u + 8) * PTOT);
            CvB[u] = __ldg(pC  + (size_t)(u + 8) * PTOT);
        }
        // compute A: t0 .. t0+7
        #pragma unroll
        for (int u = 0; u < 8; u++) {
            float dA = expf(dtA[u] * Ad);
            h = fmaf(dA, h, dtA[u] * ucA[u] * BvA[u]);
            float part = CvA[u] * h;
            part += __shfl_xor_sync(0xffffffffu, part, 8, 16);
            part += __shfl_xor_sync(0xffffffffu, part, 4, 16);
            part += __shfl_xor_sync(0xffffffffu, part, 2, 16);
            part += __shfl_xor_sync(0xffffffffu, part, 1, 16);
            if (n == 0) py[(size_t)u * DINNER] = fmaf(dsk, ucA[u], part);
        }
        // prefetch A: t0+16 .. t0+23 (guarded)
        if (t0 + 16 < SEQLEN) {
            #pragma unroll
            for (int u = 0; u < 8; u++) {
                dtA[u] = __ldg(pdt + (size_t)(u + 16) * DINNER);
                ucA[u] = __ldg(puc + (size_t)(u + 16) * DINNER);
                BvA[u] = __ldg(pB  + (size_t)(u + 16) * PTOT);
                CvA[u] = __ldg(pC  + (size_t)(u + 16) * PTOT);
            }
        }
        // compute B: t0+8 .. t0+15
        #pragma unroll
        for (int u = 0; u < 8; u++) {
            float dA = expf(dtB[u] * Ad);
            h = fmaf(dA, h, dtB[u] * ucB[u] * BvB[u]);
            float part = CvB[u] * h;
            part += __shfl_xor_sync(0xffffffffu, part, 8, 16);
            part += __shfl_xor_sync(0xffffffffu, part, 4, 16);
            part += __shfl_xor_sync(0xffffffffu, part, 2, 16);
            part += __shfl_xor_sync(0xffffffffu, part, 1, 16);
            if (n == 0) py[(size_t)(u + 8) * DINNER] = fmaf(dsk, ucB[u], part);
        }
        pB += 16 * PTOT; pC += 16 * PTOT;
        pdt += 16 * DINNER; puc += 16 * DINNER; py += 16 * DINNER;
    }
}

// ---------------------------------------------------------------------------
// gate: g = y*silu(z); gn = g * rsqrt(mean(g^2)+1e-6) * norm_w + res
// outputs split-fp16 for the output projection
// ---------------------------------------------------------------------------
__global__ void __launch_bounds__(256) gate_kernel(
    const float* __restrict__ p, const float* __restrict__ y,
    const float* __restrict__ res, const float* __restrict__ norm_w,
    __half* __restrict__ gnh, __half* __restrict__ gnl)
{
    __shared__ float sh[32];
    int r = blockIdx.x;
    const float* zrow = p + (size_t)r * PTOT + OFF_Z;
    const float* yrow = y + (size_t)r * DINNER;
    float gv[6];
    float ss = 0.f;
    #pragma unroll
    for (int i = 0; i < 6; i++) {
        int c = threadIdx.x + i * 256;
        float z = zrow[c];
        float sil = z / (1.f + expf(-z));
        float gg = yrow[c] * sil;
        gv[i] = gg;
        ss += gg * gg;
    }
    ss = block_reduce_sum256(ss, sh);
    float s = rsqrtf(ss * (1.0f / DINNER) + 1e-6f);
    #pragma unroll
    for (int i = 0; i < 6; i++) {
        int c = threadIdx.x + i * 256;
        float val = gv[i] * s * norm_w[c] + res[(size_t)r * DINNER + c];
        __half h = __float2half_rn(val);
        gnh[(size_t)r * DINNER + c] = h;
        gnl[(size_t)r * DINNER + c] = __float2half_rn(val - __half2float(h));
    }
}

// ---------------------------------------------------------------------------
// host
// ---------------------------------------------------------------------------
extern "C" void kernel_launch(void* const* d_in, const int* in_sizes, int n_in,
                              void* d_out, int out_size)
{
    const float* x       = (const float*)d_in[0];
    const float* ln_w    = (const float*)d_in[1];
    const float* ln_b    = (const float*)d_in[2];
    const float* W_in    = (const float*)d_in[3];
    const float* W_dt    = (const float*)d_in[4];
    const float* conv_w  = (const float*)d_in[5];
    const float* conv_b  = (const float*)d_in[6];
    const float* A_log   = (const float*)d_in[7];
    const float* Dskip   = (const float*)d_in[8];
    const float* dt_bias = (const float*)d_in[9];
    const float* norm_w  = (const float*)d_in[10];
    const float* W_res   = (const float*)d_in[11];
    const float* W_out   = (const float*)d_in[12];
    float* out = (float*)d_out;

    float *p, *dtpre, *dt, *uc, *y, *res;
    __half *wh, *xnh, *xh, *xl, *wres, *wout, *gnh, *gnl;
    cudaGetSymbolAddress((void**)&p,     g_p);
    cudaGetSymbolAddress((void**)&dtpre, g_dtpre);
    cudaGetSymbolAddress((void**)&dt,    g_dt);
    cudaGetSymbolAddress((void**)&uc,    g_uc);
    cudaGetSymbolAddress((void**)&y,     g_y);
    cudaGetSymbolAddress((void**)&res,   g_res);
    cudaGetSymbolAddress((void**)&wh,    g_wh);
    cudaGetSymbolAddress((void**)&xnh,   g_xnh);
    cudaGetSymbolAddress((void**)&xh,    g_xh);
    cudaGetSymbolAddress((void**)&xl,    g_xl);
    cudaGetSymbolAddress((void**)&wres,  g_wres);
    cudaGetSymbolAddress((void**)&wout,  g_wout);
    cudaGetSymbolAddress((void**)&gnh,   g_gnh);
    cudaGetSymbolAddress((void**)&gnl,   g_gnl);

    static bool attr_set = false;
    if (!attr_set) {
        cudaFuncSetAttribute(gemm1, cudaFuncAttributeMaxDynamicSharedMemorySize,
                             NSTG * STAGE1_S);
        cudaFuncSetAttribute(gemm2, cudaFuncAttributeMaxDynamicSharedMemorySize,
                             NSTG * STAGE2_S);
        attr_set = true;
    }

    // Launch order keeps gemm1 as the 4th launch (ncu profile slot).
    // 1. W_in convert (8 floats/thread)
    convert_h<<<(size_t)PTOT * DMODEL / 8 / 256, 256>>>(W_in, wh);
    // 2. LayerNorm (outputs fp16 xn)
    ln_kernel<<<NROWS, 256>>>(x, ln_w, ln_b, xnh);
    // 3. W_res convert
    convert_h<<<(size_t)DINNER * DMODEL / 8 / 256, 256>>>(W_res, wres);
    // 4. big input projection (1-term fp16): p = xn @ W_in^T  [2048, 52272]
    gemm1<<<dim3(NROWS / 128, (PTOT + 127) / 128), 256, NSTG * STAGE1_S>>>(
        xnh, wh, p, PTOT, DMODEL, DMODEL / 32);
    // 5-6. remaining converts
    convert_h<<<(size_t)DMODEL * DINNER / 8 / 256, 256>>>(W_out, wout);
    convert_split<<<(size_t)NROWS * DMODEL / 4 / 256, 256>>>(x, xh, xl);
    // 7. dt pre-projection
    gemm_nt<<<dim3(DINNER / GBN, NROWS / GBM), 256>>>(
        p + OFF_DTH, W_dt, dtpre, NROWS, DINNER, DTRANK, PTOT, DTRANK, DINNER);
    // 8. conv + softplus(dt)
    convdt_kernel<<<(NROWS * DINNER) / 256, 256>>>(
        conv_w, conv_b, dt_bias, p, dtpre, uc, dt);
    // 9. sequential SSM scan (double-buffered)
    scan_kernel<<<dim3(DINNER / 8, BATCH), 128>>>(p, dt, uc, A_log, Dskip, y);
    // 10. residual projection (2-term)
    gemm2<<<dim3(NROWS / 128, DINNER / 128), 256, NSTG * STAGE2_S>>>(
        xh, xl, wres, res, DINNER, DMODEL, DMODEL / 32);
    // 11. gate + RMSNorm + residual
    gate_kernel<<<NROWS, 256>>>(p, y, res, norm_w, gnh, gnl);
    // 12. output projection (2-term)
    gemm2<<<dim3(NROWS / 128, DMODEL / 128), 256, NSTG * STAGE2_S>>>(
        gnh, gnl, wout, out, DMODEL, DINNER, DINNER / 32);
}

// round 12
// speedup vs baseline: 1.7218x; 1.0414x over previous
#include <cuda_runtime.h>
#include <cuda_bf16.h>
#include <cuda_fp16.h>
#include <math.h>
#include <stdint.h>

// ---------------------------------------------------------------------------
// HybridMambaBlock: B=2, L=1024, D_MODEL=768, D=1536, N=16, K_CONV=4, R=48
// p layout per token (52272): [z:0..1536) [u:1536..3072) [dth:3072..3120)
//                             [B:3120..27696) [C:27696..52272)
// ---------------------------------------------------------------------------

#define BATCH   2
#define SEQLEN  1024
#define NROWS   (BATCH*SEQLEN)      // 2048
#define DMODEL  768
#define DINNER  1536
#define NSTATE  16
#define DTRANK  48
#define PTOT    52272
#define OFF_Z   0
#define OFF_U   1536
#define OFF_DTH 3072
#define OFF_B   3120
#define OFF_C   27696

// scratch (device-global: no allocations allowed)
__device__ float g_p[(size_t)NROWS * PTOT];          // ~428 MB
__device__ float g_dtpre[(size_t)NROWS * DINNER];
__device__ float g_dt[(size_t)NROWS * DINNER];
__device__ float g_uc[(size_t)NROWS * DINNER];
__device__ float g_y[(size_t)NROWS * DINNER];
__device__ float g_res[(size_t)NROWS * DINNER];
__device__ __half g_wh[(size_t)PTOT * DMODEL];       // 80 MB fp16 W_in
__device__ __half g_xnh[(size_t)NROWS * DMODEL];
__device__ __half g_xh[(size_t)NROWS * DMODEL];
__device__ __half g_xl[(size_t)NROWS * DMODEL];
__device__ __half g_wres[(size_t)DINNER * DMODEL];
__device__ __half g_wout[(size_t)DMODEL * DINNER];
__device__ __half g_gnh[(size_t)NROWS * DINNER];
__device__ __half g_gnl[(size_t)NROWS * DINNER];

// ---------------------------------------------------------------------------
// helpers
// ---------------------------------------------------------------------------
__device__ __forceinline__ uint32_t smem_u32(const void* p) {
    uint32_t a;
    asm("{ .reg .u64 t; cvta.to.shared.u64 t, %1; cvt.u32.u64 %0, t; }"
        : "=r"(a) : "l"(p));
    return a;
}

#define LDSM4(r0, r1, r2, r3, addr) \
    asm volatile("ldmatrix.sync.aligned.m8n8.x4.shared.b16 {%0,%1,%2,%3}, [%4];" \
        : "=r"(r0), "=r"(r1), "=r"(r2), "=r"(r3) : "r"(addr))

#define MMA16816F16(d, a, b) \
    asm volatile("mma.sync.aligned.m16n8k16.row.col.f32.f16.f16.f32 " \
        "{%0,%1,%2,%3}, {%4,%5,%6,%7}, {%8,%9}, {%0,%1,%2,%3};" \
        : "+f"((d)[0]), "+f"((d)[1]), "+f"((d)[2]), "+f"((d)[3]) \
        : "r"((a)[0]), "r"((a)[1]), "r"((a)[2]), "r"((a)[3]), \
          "r"((b)[0]), "r"((b)[1]))

#define CP_ASYNC16(dst, src, zf) \
    asm volatile("cp.async.cg.shared.global [%0], [%1], 16, %2;" \
        :: "r"(dst), "l"(src), "r"(zf))
#define CP_COMMIT()  asm volatile("cp.async.commit_group;" ::: "memory")
#define CP_WAIT1()   asm volatile("cp.async.wait_group 1;" ::: "memory")

#define ROWB    80
#define TILE_S  (128 * ROWB)         // 10240 B per 128x32 fp16 tile
#define NSTG    3

// ---------------------------------------------------------------------------
// 1-term fp16 HMMA GEMM (big projection):  C[m,n] = sum_k Ah[m,k] * Wh[n,k]
// CTA 128x128, BK=32, 3-stage cp.async, 8 warps of 32x64, 2 CTAs/SM.
// At the mma.sync issue floor (~520us) — do not touch.
// ---------------------------------------------------------------------------
#define STAGE1_S (2 * TILE_S)        // Ah Wh

__global__ void __launch_bounds__(256, 2) gemm1(
    const __half* __restrict__ Ah, const __half* __restrict__ Wh,
    float* __restrict__ C, int N, int K, int kiter)
{
    extern __shared__ char sm[];
    uint32_t sb = smem_u32(sm);
    int tid = threadIdx.x;
    int wid = tid >> 5;
    int lane = tid & 31;
    int m0 = blockIdx.x * 128;
    int n0 = blockIdx.y * 128;
    int wm = wid >> 1;
    int wn = wid & 1;

    auto load_stage = [&](int stage, int k0) {
        uint32_t sdst = sb + stage * STAGE1_S;
        #pragma unroll
        for (int j = 0; j < 4; j++) {
            int job = tid + j * 256;     // 0..1023
            int tile = job >> 9;         // 0=Ah 1=Wh
            int rem  = job & 511;
            int r    = rem >> 2;
            int cc   = rem & 3;
            const __half* src;
            int zf = 16;
            if (tile == 0) src = Ah + (size_t)(m0 + r) * K + k0 + cc * 8;
            else {
                int n = n0 + r;
                if (n >= N) { n = N - 1; zf = 0; }
                src = Wh + (size_t)n * K + k0 + cc * 8;
            }
            uint32_t d = sdst + tile * TILE_S + r * ROWB + cc * 16;
            CP_ASYNC16(d, src, zf);
        }
        CP_COMMIT();
    };

    float c[2][8][4];
    #pragma unroll
    for (int mt = 0; mt < 2; mt++)
        #pragma unroll
        for (int nt = 0; nt < 8; nt++)
            #pragma unroll
            for (int q = 0; q < 4; q++) c[mt][nt][q] = 0.f;

    load_stage(0, 0);
    load_stage(1, 32);

    for (int it = 0; it < kiter; it++) {
        CP_WAIT1();
        __syncthreads();

        int k0n = (it + 2) * 32;
        if (k0n < K) load_stage((it + 2) % NSTG, k0n);
        else CP_COMMIT();

        uint32_t st = sb + (it % NSTG) * STAGE1_S;

        #pragma unroll
        for (int kk = 0; kk < 32; kk += 16) {
            uint32_t aH[2][4], bH[8][2];
            #pragma unroll
            for (int mt = 0; mt < 2; mt++) {
                int row = wm * 32 + mt * 16 + (lane & 15);
                int ch  = (kk >> 3) + (lane >> 4);
                uint32_t addr = st + row * ROWB + ch * 16;
                LDSM4(aH[mt][0], aH[mt][1], aH[mt][2], aH[mt][3], addr);
            }
            #pragma unroll
            for (int np = 0; np < 4; np++) {
                int nrow = wn * 64 + np * 16 + (lane & 7) + ((lane >> 4) << 3);
                int ch   = (kk >> 3) + ((lane >> 3) & 1);
                uint32_t addr = st + TILE_S + nrow * ROWB + ch * 16;
                LDSM4(bH[np * 2][0], bH[np * 2][1], bH[np * 2 + 1][0], bH[np * 2 + 1][1], addr);
            }
            #pragma unroll
            for (int mt = 0; mt < 2; mt++)
                #pragma unroll
                for (int nt = 0; nt < 8; nt++)
                    MMA16816F16(c[mt][nt], aH[mt], bH[nt]);
        }
        __syncthreads();
    }

    int g = lane >> 2, t4 = lane & 3;
    #pragma unroll
    for (int mt = 0; mt < 2; mt++) {
        int row = m0 + wm * 32 + mt * 16 + g;
        #pragma unroll
        for (int nt = 0; nt < 8; nt++) {
            int col = n0 + wn * 64 + nt * 8 + t4 * 2;
            if (col < N) {
                float2 v0 = make_float2(c[mt][nt][0], c[mt][nt][1]);
                float2 v1 = make_float2(c[mt][nt][2], c[mt][nt][3]);
                *(float2*)(C + (size_t)row * N + col) = v0;
                *(float2*)(C + (size_t)(row + 8) * N + col) = v1;
            }
        }
    }
}

// ---------------------------------------------------------------------------
// 2-term split-fp16 HMMA GEMM (res/out): C = (Ah+Al) @ Wh^T
// ---------------------------------------------------------------------------
#define STAGE2_S (3 * TILE_S)        // Ah Al Wh

__global__ void __launch_bounds__(256, 1) gemm2(
    const __half* __restrict__ Ah, const __half* __restrict__ Al,
    const __half* __restrict__ Wh, float* __restrict__ C,
    int N, int K, int kiter)
{
    extern __shared__ char sm[];
    uint32_t sb = smem_u32(sm);
    int tid = threadIdx.x;
    int wid = tid >> 5;
    int lane = tid & 31;
    int m0 = blockIdx.x * 128;
    int n0 = blockIdx.y * 128;
    int wm = wid >> 1;
    int wn = wid & 1;

    auto load_stage = [&](int stage, int k0) {
        uint32_t sdst = sb + stage * STAGE2_S;
        #pragma unroll
        for (int j = 0; j < 6; j++) {
            int job = tid + j * 256;
            int tile = job >> 9;         // 0=Ah 1=Al 2=Wh
            int rem  = job & 511;
            int r    = rem >> 2;
            int cc   = rem & 3;
            const __half* src;
            int zf = 16;
            if (tile == 0)      src = Ah + (size_t)(m0 + r) * K + k0 + cc * 8;
            else if (tile == 1) src = Al + (size_t)(m0 + r) * K + k0 + cc * 8;
            else {
                int n = n0 + r;
                if (n >= N) { n = N - 1; zf = 0; }
                src = Wh + (size_t)n * K + k0 + cc * 8;
            }
            uint32_t d = sdst + tile * TILE_S + r * ROWB + cc * 16;
            CP_ASYNC16(d, src, zf);
        }
        CP_COMMIT();
    };

    float c[2][8][4];
    #pragma unroll
    for (int mt = 0; mt < 2; mt++)
        #pragma unroll
        for (int nt = 0; nt < 8; nt++)
            #pragma unroll
            for (int q = 0; q < 4; q++) c[mt][nt][q] = 0.f;

    load_stage(0, 0);
    load_stage(1, 32);

    for (int it = 0; it < kiter; it++) {
        CP_WAIT1();
        __syncthreads();

        int k0n = (it + 2) * 32;
        if (k0n < K) load_stage((it + 2) % NSTG, k0n);
        else CP_COMMIT();

        uint32_t st = sb + (it % NSTG) * STAGE2_S;

        #pragma unroll
        for (int kk = 0; kk < 32; kk += 16) {
            uint32_t aH[2][4], aL[2][4], bH[8][2];
            #pragma unroll
            for (int mt = 0; mt < 2; mt++) {
                int row = wm * 32 + mt * 16 + (lane & 15);
                int ch  = (kk >> 3) + (lane >> 4);
                uint32_t addr = st + row * ROWB + ch * 16;
                LDSM4(aH[mt][0], aH[mt][1], aH[mt][2], aH[mt][3], addr);
                LDSM4(aL[mt][0], aL[mt][1], aL[mt][2], aL[mt][3], addr + TILE_S);
            }
            #pragma unroll
            for (int np = 0; np < 4; np++) {
                int nrow = wn * 64 + np * 16 + (lane & 7) + ((lane >> 4) << 3);
                int ch   = (kk >> 3) + ((lane >> 3) & 1);
                uint32_t addr = st + 2 * TILE_S + nrow * ROWB + ch * 16;
                LDSM4(bH[np * 2][0], bH[np * 2][1], bH[np * 2 + 1][0], bH[np * 2 + 1][1], addr);
            }
            #pragma unroll
            for (int mt = 0; mt < 2; mt++)
                #pragma unroll
                for (int nt = 0; nt < 8; nt++) {
                    MMA16816F16(c[mt][nt], aH[mt], bH[nt]);
                    MMA16816F16(c[mt][nt], aL[mt], bH[nt]);
                }
        }
        __syncthreads();
    }

    int g = lane >> 2, t4 = lane & 3;
    #pragma unroll
    for (int mt = 0; mt < 2; mt++) {
        int row = m0 + wm * 32 + mt * 16 + g;
        #pragma unroll
        for (int nt = 0; nt < 8; nt++) {
            int col = n0 + wn * 64 + nt * 8 + t4 * 2;
            if (col < N) {
                float2 v0 = make_float2(c[mt][nt][0], c[mt][nt][1]);
                float2 v1 = make_float2(c[mt][nt][2], c[mt][nt][3]);
                *(float2*)(C + (size_t)row * N + col) = v0;
                *(float2*)(C + (size_t)(row + 8) * N + col) = v1;
            }
        }
    }
}

// ---------------------------------------------------------------------------
// fp32 -> fp16 (hi only): 8 floats per thread, single 16B store
// ---------------------------------------------------------------------------
__global__ void __launch_bounds__(256) convert_h(
    const float* __restrict__ W, __half* __restrict__ Wh)
{
    size_t i8 = (size_t)blockIdx.x * 256 + threadIdx.x;  // 8-float chunk idx
    const float4* W4 = (const float4*)W;
    float4 a = W4[i8 * 2 + 0];
    float4 b = W4[i8 * 2 + 1];
    __half2 h[4];
    h[0] = __floats2half2_rn(a.x, a.y);
    h[1] = __floats2half2_rn(a.z, a.w);
    h[2] = __floats2half2_rn(b.x, b.y);
    h[3] = __floats2half2_rn(b.z, b.w);
    ((uint4*)Wh)[i8] = *(uint4*)h;
}

// ---------------------------------------------------------------------------
// fp32 -> (hi, lo) fp16 split
// ---------------------------------------------------------------------------
__global__ void __launch_bounds__(256) convert_split(
    const float* __restrict__ X, __half* __restrict__ Xh, __half* __restrict__ Xl)
{
    size_t i4 = (size_t)blockIdx.x * 256 + threadIdx.x;
    float4 v = ((const float4*)X)[i4];
    __half h0 = __float2half_rn(v.x), h1 = __float2half_rn(v.y);
    __half h2 = __float2half_rn(v.z), h3 = __float2half_rn(v.w);
    __half2* oh = (__half2*)Xh;
    __half2* ol = (__half2*)Xl;
    oh[i4 * 2 + 0] = __halves2half2(h0, h1);
    oh[i4 * 2 + 1] = __halves2half2(h2, h3);
    ol[i4 * 2 + 0] = __floats2half2_rn(v.x - __half2float(h0), v.y - __half2float(h1));
    ol[i4 * 2 + 1] = __floats2half2_rn(v.z - __half2float(h2), v.w - __half2float(h3));
}

// ---------------------------------------------------------------------------
// block reduction helper (256 threads)
// ---------------------------------------------------------------------------
__device__ __forceinline__ float block_reduce_sum256(float v, float* sh) {
    int lane = threadIdx.x & 31;
    int w    = threadIdx.x >> 5;
    #pragma unroll
    for (int o = 16; o > 0; o >>= 1) v += __shfl_xor_sync(0xffffffffu, v, o);
    if (lane == 0) sh[w] = v;
    __syncthreads();
    if (w == 0) {
        v = (lane < 8) ? sh[lane] : 0.0f;
        #pragma unroll
        for (int o = 4; o > 0; o >>= 1) v += __shfl_xor_sync(0xffffffffu, v, o);
        if (lane == 0) sh[0] = v;
    }
    __syncthreads();
    return sh[0];
}

// ---------------------------------------------------------------------------
// LayerNorm: one block per row of 768; outputs fp16 xn
// ---------------------------------------------------------------------------
__global__ void __launch_bounds__(256) ln_kernel(
    const float* __restrict__ x, const float* __restrict__ w,
    const float* __restrict__ b, __half* __restrict__ oh)
{
    __shared__ float sh[32];
    int r = blockIdx.x;
    const float* xr = x + (size_t)r * DMODEL;
    float s = 0.f, ss = 0.f;
    float v[3];
    #pragma unroll
    for (int i = 0; i < 3; i++) {
        v[i] = xr[threadIdx.x + i * 256];
        s  += v[i];
        ss += v[i] * v[i];
    }
    s  = block_reduce_sum256(s, sh);
    __syncthreads();
    ss = block_reduce_sum256(ss, sh);
    float mu  = s * (1.0f / DMODEL);
    float var = ss * (1.0f / DMODEL) - mu * mu;
    float inv = rsqrtf(var + 1e-5f);
    #pragma unroll
    for (int i = 0; i < 3; i++) {
        int c = threadIdx.x + i * 256;
        float val = (v[i] - mu) * inv * w[c] + b[c];
        oh[(size_t)r * DMODEL + c] = __float2half_rn(val);
    }
}

// ---------------------------------------------------------------------------
// SIMT fp32 GEMM (dt projection only, K=48): C[m,n] = sum_k A[m,k]*B[n,k]
// ---------------------------------------------------------------------------
#define GBM 128
#define GBN 128
#define GBK 16
__global__ void __launch_bounds__(256) gemm_nt(
    const float* __restrict__ A, const float* __restrict__ B,
    float* __restrict__ C, int M, int N, int K, int lda, int ldb, int ldc)
{
    __shared__ float As[GBK][GBM + 4];
    __shared__ float Bs[GBK][GBN + 4];

    int tid = threadIdx.x;
    int tx = tid & 15;
    int ty = tid >> 4;
    int m0 = blockIdx.y * GBM;
    int n0 = blockIdx.x * GBN;
    int lrow = tid >> 2;
    int lc4  = tid & 3;

    float acc[8][8];
    #pragma unroll
    for (int i = 0; i < 8; i++)
        #pragma unroll
        for (int j = 0; j < 8; j++) acc[i][j] = 0.f;

    for (int k0 = 0; k0 < K; k0 += GBK) {
        #pragma unroll
        for (int i = 0; i < 2; i++) {
            int row = lrow + i * 64;
            float4 v = *(const float4*)(A + (size_t)(m0 + row) * lda + k0 + lc4 * 4);
            As[lc4 * 4 + 0][row] = v.x;
            As[lc4 * 4 + 1][row] = v.y;
            As[lc4 * 4 + 2][row] = v.z;
            As[lc4 * 4 + 3][row] = v.w;
        }
        #pragma unroll
        for (int i = 0; i < 2; i++) {
            int row = lrow + i * 64;
            int n = n0 + row;
            float4 v = make_float4(0.f, 0.f, 0.f, 0.f);
            if (n < N)
                v = *(const float4*)(B + (size_t)n * ldb + k0 + lc4 * 4);
            Bs[lc4 * 4 + 0][row] = v.x;
            Bs[lc4 * 4 + 1][row] = v.y;
            Bs[lc4 * 4 + 2][row] = v.z;
            Bs[lc4 * 4 + 3][row] = v.w;
        }
        __syncthreads();
        #pragma unroll
        for (int kk = 0; kk < GBK; kk++) {
            float a[8], b[8];
            #pragma unroll
            for (int i = 0; i < 8; i++) a[i] = As[kk][ty * 8 + i];
            #pragma unroll
            for (int j = 0; j < 8; j++) b[j] = Bs[kk][tx * 8 + j];
            #pragma unroll
            for (int i = 0; i < 8; i++)
                #pragma unroll
                for (int j = 0; j < 8; j++)
                    acc[i][j] = fmaf(a[i], b[j], acc[i][j]);
        }
        __syncthreads();
    }

    #pragma unroll
    for (int i = 0; i < 8; i++) {
        int m = m0 + ty * 8 + i;
        float* cp = C + (size_t)m * ldc + n0 + tx * 8;
        float4 v0 = make_float4(acc[i][0], acc[i][1], acc[i][2], acc[i][3]);
        float4 v1 = make_float4(acc[i][4], acc[i][5], acc[i][6], acc[i][7]);
        *(float4*)(cp + 0) = v0;
        *(float4*)(cp + 4) = v1;
    }
}

// ---------------------------------------------------------------------------
// Depthwise causal conv (K=4) + dt = clip(softplus(dtpre + dt_bias))
// ---------------------------------------------------------------------------
__global__ void __launch_bounds__(256) convdt_kernel(
    const float* __restrict__ conv_w, const float* __restrict__ conv_b,
    const float* __restrict__ dt_bias,
    const float* __restrict__ p, const float* __restrict__ dtpre,
    float* __restrict__ uc, float* __restrict__ dt)
{
    int idx = blockIdx.x * 256 + threadIdx.x;
    int d = idx % DINNER;
    int r = idx / DINNER;
    int l = r & (SEQLEN - 1);

    const float* pu = p + (size_t)r * PTOT + OFF_U + d;
    float acc = conv_b[d];
    #pragma unroll
    for (int k = 0; k < 4; k++) {
        int lp = l - 3 + k;
        if (lp >= 0)
            acc = fmaf(pu[(ptrdiff_t)(k - 3) * PTOT], conv_w[d * 4 + k], acc);
    }
    uc[idx] = acc;

    float xv = dtpre[idx] + dt_bias[d];
    float sp = fmaxf(xv, 0.f) + log1pf(expf(-fabsf(xv)));
    dt[idx] = fminf(fmaxf(sp, 1e-4f), 1.0f);
}

// ---------------------------------------------------------------------------
// SSM scan v2: 16 threads per (b,d), 128-thread blocks (8 groups), grid 384.
// Double-buffered software pipeline.
// ---------------------------------------------------------------------------
__global__ void __launch_bounds__(128) scan_kernel(
    const float* __restrict__ p, const float* __restrict__ dt,
    const float* __restrict__ uc, const float* __restrict__ A_log,
    const float* __restrict__ Dskip, float* __restrict__ y)
{
    int tid = threadIdx.x;
    int n = tid & 15;
    int g = tid >> 4;                   // 0..7
    int d = blockIdx.x * 8 + g;
    int b = blockIdx.y;

    float Ad  = -expf(A_log[d * NSTATE + n]);
    float dsk = Dskip[d];
    float h = 0.f;

    const float* pB  = p  + (size_t)(b * SEQLEN) * PTOT + OFF_B + d * NSTATE + n;
    const float* pC  = pB + (OFF_C - OFF_B);
    const float* pdt = dt + (size_t)(b * SEQLEN) * DINNER + d;
    const float* puc = uc + (size_t)(b * SEQLEN) * DINNER + d;
    float*       py  = y  + (size_t)(b * SEQLEN) * DINNER + d;

    float dtA[8], ucA[8], BvA[8], CvA[8];
    float dtB[8], ucB[8], BvB[8], CvB[8];

    // prime buffer A with t = 0..7
    #pragma unroll
    for (int u = 0; u < 8; u++) {
        dtA[u] = __ldg(pdt + (size_t)u * DINNER);
        ucA[u] = __ldg(puc + (size_t)u * DINNER);
        BvA[u] = __ldg(pB  + (size_t)u * PTOT);
        CvA[u] = __ldg(pC  + (size_t)u * PTOT);
    }

    for (int t0 = 0; t0 < SEQLEN; t0 += 16) {
        // prefetch B: t0+8 .. t0+15
        #pragma unroll
        for (int u = 0; u < 8; u++) {
            dtB[u] = __ldg(pdt + (size_t)(u + 8) * DINNER);
            ucB[u] = __ldg(puc + (size_t)(u + 8) * DINNER);
            BvB[u] = __ldg(pB  + (size_t)(u + 8) * PTOT);
            CvB[u] = __ldg(pC  + (size_t)(u + 8) * PTOT);
        }
        // compute A: t0 .. t0+7
        #pragma unroll
        for (int u = 0; u < 8; u++) {
            float dA = expf(dtA[u] * Ad);
            h = fmaf(dA, h, dtA[u] * ucA[u] * BvA[u]);
            float part = CvA[u] * h;
            part += __shfl_xor_sync(0xffffffffu, part, 8, 16);
            part += __shfl_xor_sync(0xffffffffu, part, 4, 16);
            part += __shfl_xor_sync(0xffffffffu, part, 2, 16);
            part += __shfl_xor_sync(0xffffffffu, part, 1, 16);
            if (n == 0) py[(size_t)u * DINNER] = fmaf(dsk, ucA[u], part);
        }
        // prefetch A: t0+16 .. t0+23 (guarded)
        if (t0 + 16 < SEQLEN) {
            #pragma unroll
            for (int u = 0; u < 8; u++) {
                dtA[u] = __ldg(pdt + (size_t)(u + 16) * DINNER);
                ucA[u] = __ldg(puc + (size_t)(u + 16) * DINNER);
                BvA[u] = __ldg(pB  + (size_t)(u + 16) * PTOT);
                CvA[u] = __ldg(pC  + (size_t)(u + 16) * PTOT);
            }
        }
        // compute B: t0+8 .. t0+15
        #pragma unroll
        for (int u = 0; u < 8; u++) {
            float dA = expf(dtB[u] * Ad);
            h = fmaf(dA, h, dtB[u] * ucB[u] * BvB[u]);
            float part = CvB[u] * h;
            part += __shfl_xor_sync(0xffffffffu, part, 8, 16);
            part += __shfl_xor_sync(0xffffffffu, part, 4, 16);
            part += __shfl_xor_sync(0xffffffffu, part, 2, 16);
            part += __shfl_xor_sync(0xffffffffu, part, 1, 16);
            if (n == 0) py[(size_t)(u + 8) * DINNER] = fmaf(dsk, ucB[u], part);
        }
        pB += 16 * PTOT; pC += 16 * PTOT;
        pdt += 16 * DINNER; puc += 16 * DINNER; py += 16 * DINNER;
    }
}

// ---------------------------------------------------------------------------
// gate: g = y*silu(z); gn = g * rsqrt(mean(g^2)+1e-6) * norm_w + res
// outputs split-fp16 for the output projection
// ---------------------------------------------------------------------------
__global__ void __launch_bounds__(256) gate_kernel(
    const float* __restrict__ p, const float* __restrict__ y,
    const float* __restrict__ res, const float* __restrict__ norm_w,
    __half* __restrict__ gnh, __half* __restrict__ gnl)
{
    __shared__ float sh[32];
    int r = blockIdx.x;
    const float* zrow = p + (size_t)r * PTOT + OFF_Z;
    const float* yrow = y + (size_t)r * DINNER;
    float gv[6];
    float ss = 0.f;
    #pragma unroll
    for (int i = 0; i < 6; i++) {
        int c = threadIdx.x + i * 256;
        float z = zrow[c];
        float sil = z / (1.f + expf(-z));
        float gg = yrow[c] * sil;
        gv[i] = gg;
        ss += gg * gg;
    }
    ss = block_reduce_sum256(ss, sh);
    float s = rsqrtf(ss * (1.0f / DINNER) + 1e-6f);
    #pragma unroll
    for (int i = 0; i < 6; i++) {
        int c = threadIdx.x + i * 256;
        float val = gv[i] * s * norm_w[c] + res[(size_t)r * DINNER + c];
        __half h = __float2half_rn(val);
        gnh[(size_t)r * DINNER + c] = h;
        gnl[(size_t)r * DINNER + c] = __float2half_rn(val - __half2float(h));
    }
}

// ---------------------------------------------------------------------------
// host
// ---------------------------------------------------------------------------
extern "C" void kernel_launch(void* const* d_in, const int* in_sizes, int n_in,
                              void* d_out, int out_size)
{
    const float* x       = (const float*)d_in[0];
    const float* ln_w    = (const float*)d_in[1];
    const float* ln_b    = (const float*)d_in[2];
    const float* W_in    = (const float*)d_in[3];
    const float* W_dt    = (const float*)d_in[4];
    const float* conv_w  = (const float*)d_in[5];
    const float* conv_b  = (const float*)d_in[6];
    const float* A_log   = (const float*)d_in[7];
    const float* Dskip   = (const float*)d_in[8];
    const float* dt_bias = (const float*)d_in[9];
    const float* norm_w  = (const float*)d_in[10];
    const float* W_res   = (const float*)d_in[11];
    const float* W_out   = (const float*)d_in[12];
    float* out = (float*)d_out;

    float *p, *dtpre, *dt, *uc, *y, *res;
    __half *wh, *xnh, *xh, *xl, *wres, *wout, *gnh, *gnl;
    cudaGetSymbolAddress((void**)&p,     g_p);
    cudaGetSymbolAddress((void**)&dtpre, g_dtpre);
    cudaGetSymbolAddress((void**)&dt,    g_dt);
    cudaGetSymbolAddress((void**)&uc,    g_uc);
    cudaGetSymbolAddress((void**)&y,     g_y);
    cudaGetSymbolAddress((void**)&res,   g_res);
    cudaGetSymbolAddress((void**)&wh,    g_wh);
    cudaGetSymbolAddress((void**)&xnh,   g_xnh);
    cudaGetSymbolAddress((void**)&xh,    g_xh);
    cudaGetSymbolAddress((void**)&xl,    g_xl);
    cudaGetSymbolAddress((void**)&wres,  g_wres);
    cudaGetSymbolAddress((void**)&wout,  g_wout);
    cudaGetSymbolAddress((void**)&gnh,   g_gnh);
    cudaGetSymbolAddress((void**)&gnl,   g_gnl);

    static bool init_done = false;
    static cudaStream_t s_side;
    static cudaEvent_t ev_fork, ev_join;
    if (!init_done) {
        cudaFuncSetAttribute(gemm1, cudaFuncAttributeMaxDynamicSharedMemorySize,
                             NSTG * STAGE1_S);
        cudaFuncSetAttribute(gemm2, cudaFuncAttributeMaxDynamicSharedMemorySize,
                             NSTG * STAGE2_S);
        cudaStreamCreateWithFlags(&s_side, cudaStreamNonBlocking);
        cudaEventCreateWithFlags(&ev_fork, cudaEventDisableTiming);
        cudaEventCreateWithFlags(&ev_join, cudaEventDisableTiming);
        init_done = true;
    }

    // ---- main stream (0): critical path through gemm1 + scan ----
    // 1. W_in convert
    convert_h<<<(size_t)PTOT * DMODEL / 8 / 256, 256>>>(W_in, wh);
    // 2. LayerNorm (outputs fp16 xn)
    ln_kernel<<<NROWS, 256>>>(x, ln_w, ln_b, xnh);

    // fork: side stream handles the gemm1-independent res-chain
    cudaEventRecord(ev_fork, 0);
    cudaStreamWaitEvent(s_side, ev_fork, 0);
    // 3. W_res convert [side]
    convert_h<<<(size_t)DINNER * DMODEL / 8 / 256, 256, 0, s_side>>>(W_res, wres);

    // 4. big input projection (1-term fp16): p = xn @ W_in^T  [2048, 52272]
    gemm1<<<dim3(NROWS / 128, (PTOT + 127) / 128), 256, NSTG * STAGE1_S>>>(
        xnh, wh, p, PTOT, DMODEL, DMODEL / 32);

    // 5-7. [side] x split, W_out convert, residual projection (2-term)
    convert_split<<<(size_t)NROWS * DMODEL / 4 / 256, 256, 0, s_side>>>(x, xh, xl);
    convert_h<<<(size_t)DMODEL * DINNER / 8 / 256, 256, 0, s_side>>>(W_out, wout);
    gemm2<<<dim3(NROWS / 128, DINNER / 128), 256, NSTG * STAGE2_S, s_side>>>(
        xh, xl, wres, res, DINNER, DMODEL, DMODEL / 32);
    cudaEventRecord(ev_join, s_side);

    // 8. dt pre-projection [main]
    gemm_nt<<<dim3(DINNER / GBN, NROWS / GBM), 256>>>(
        p + OFF_DTH, W_dt, dtpre, NROWS, DINNER, DTRANK, PTOT, DTRANK, DINNER);
    // 9. conv + softplus(dt)
    convdt_kernel<<<(NROWS * DINNER) / 256, 256>>>(
        conv_w, conv_b, dt_bias, p, dtpre, uc, dt);
    // 10. sequential SSM scan (double-buffered)
    scan_kernel<<<dim3(DINNER / 8, BATCH), 128>>>(p, dt, uc, A_log, Dskip, y);

    // join: gate needs res (side) + y (main)
    cudaStreamWaitEvent(0, ev_join, 0);
    // 11. gate + RMSNorm + residual
    gate_kernel<<<NROWS, 256>>>(p, y, res, norm_w, gnh, gnl);
    // 12. output projection (2-term)
    gemm2<<<dim3(NROWS / 128, DMODEL / 128), 256, NSTG * STAGE2_S>>>(
        gnh, gnl, wout, out, DMODEL, DINNER, DINNER / 32);
}